// round 11
// baseline (speedup 1.0000x reference)
#include <cuda_runtime.h>
#include <cuda_bf16.h>
#include <stdint.h>
#include <math.h>

// Problem constants
#define LQ    21760
#define NB    2
#define CC    256
#define NHEAD 8
#define FFD   1024
#define NLAY  6
#define NROW  (NB*LQ)        // 43520

// packed weight layout per layer (all [N][K] bf16)
#define VOA_SZ   163840      // 640 x 256
#define WO_OFF   163840      // 256 x 256
#define W1_OFF   229376      // 1024 x 256
#define W2_OFF   491520      // 256 x 1024
#define WTOT     753664

// ---------------- device scratch ----------------
__device__ float g_xp  [NROW*CC];        // x + pos (f32, residual for LN1)
__device__ float g_voa [NROW*640];       // [v(256) | off(256) | att(128)]
__device__ float g_tmp [NROW*CC];        // Wo out / W2 out
__device__ __nv_bfloat16 g_ahi[NROW*CC]; // activation split (xp / samp / x)
__device__ __nv_bfloat16 g_alo[NROW*CC];
__device__ __nv_bfloat16 g_bhi[NROW*FFD];// FFN hidden split
__device__ __nv_bfloat16 g_blo[NROW*FFD];
__device__ __nv_bfloat16 g_whi[NLAY*WTOT];
__device__ __nv_bfloat16 g_wlo[NLAY*WTOT];
__device__ float g_bvoa[NLAY*640];       // packed bias for voa GEMM

// ======================= helpers =======================
__device__ __forceinline__ uint32_t smem_u32(const void* p) {
    uint32_t a;
    asm("{ .reg .u64 t; cvta.to.shared.u64 t, %1; cvt.u32.u64 %0, t; }"
        : "=r"(a) : "l"(p));
    return a;
}
__device__ __forceinline__ void cp16(uint32_t dst, const void* src) {
    asm volatile("cp.async.cg.shared.global [%0], [%1], 16;"
                 :: "r"(dst), "l"(src) : "memory");
}
__device__ __forceinline__ void cp_commit() {
    asm volatile("cp.async.commit_group;" ::: "memory");
}
template <int N>
__device__ __forceinline__ void cp_wait() {
    asm volatile("cp.async.wait_group %0;" :: "n"(N) : "memory");
}
__device__ __forceinline__ void ldsm4(uint32_t* r, uint32_t addr) {
    asm volatile("ldmatrix.sync.aligned.m8n8.x4.shared.b16 {%0,%1,%2,%3}, [%4];"
                 : "=r"(r[0]), "=r"(r[1]), "=r"(r[2]), "=r"(r[3]) : "r"(addr));
}
__device__ __forceinline__ void ldsm2(uint32_t* r, uint32_t addr) {
    asm volatile("ldmatrix.sync.aligned.m8n8.x2.shared.b16 {%0,%1}, [%2];"
                 : "=r"(r[0]), "=r"(r[1]) : "r"(addr));
}
__device__ __forceinline__ void mma_bf16(float* c, const uint32_t* a, const uint32_t* b) {
    asm volatile(
        "mma.sync.aligned.m16n8k16.row.col.f32.bf16.bf16.f32 "
        "{%0,%1,%2,%3}, {%4,%5,%6,%7}, {%8,%9}, {%0,%1,%2,%3};"
        : "+f"(c[0]), "+f"(c[1]), "+f"(c[2]), "+f"(c[3])
        : "r"(a[0]), "r"(a[1]), "r"(a[2]), "r"(a[3]), "r"(b[0]), "r"(b[1]));
}
__device__ __forceinline__ void split1(float v, __nv_bfloat16& h, __nv_bfloat16& l) {
    h = __float2bfloat16_rn(v);
    l = __float2bfloat16_rn(v - __bfloat162float(h));
}

// ======================= HMMA GEMM (3-term bf16 split) =======================
// Round-6 body (no min-blocks clamp, ldsm2 B loads) + 3-stage cp.async pipeline.
#define STAGE_BYTES 40960
#define NSTAGE 3
#define ROW_ELT 40

__global__ __launch_bounds__(256)
void gemm_bf16x3(const __nv_bfloat16* __restrict__ Ah,
                 const __nv_bfloat16* __restrict__ Al,
                 const __nv_bfloat16* __restrict__ Bh,
                 const __nv_bfloat16* __restrict__ Bl,
                 const float* __restrict__ bias,
                 float* __restrict__ Cf,
                 __nv_bfloat16* __restrict__ Chi,
                 __nv_bfloat16* __restrict__ Clo,
                 int K, int N, int do_relu)
{
    extern __shared__ __align__(128) char smem[];
    const uint32_t sb = smem_u32(smem);
    const int tid    = threadIdx.x;
    const int lane   = tid & 31;
    const int wid    = tid >> 5;
    const int warp_m = wid >> 2;
    const int warp_n = wid & 3;
    const int bm     = blockIdx.x * 128;
    const int bn     = blockIdx.y * 128;

    const __nv_bfloat16* gsrc[8];
    uint32_t soff[8];
    #pragma unroll
    for (int i = 0; i < 8; i++) {
        int q   = tid + i * 256;
        int arr = q >> 9;
        int rem = q & 511;
        int row = rem >> 2;
        int kc  = (rem & 3) << 3;
        const __nv_bfloat16* base =
            (arr == 0) ? Ah + (size_t)(bm + row) * K :
            (arr == 1) ? Al + (size_t)(bm + row) * K :
            (arr == 2) ? Bh + (size_t)(bn + row) * K :
                         Bl + (size_t)(bn + row) * K;
        gsrc[i] = base + kc;
        soff[i] = (uint32_t)(arr * 10240 + (row * ROW_ELT + kc) * 2);
    }

    float acc[4][4][4];
    #pragma unroll
    for (int mf = 0; mf < 4; mf++)
        #pragma unroll
        for (int nf = 0; nf < 4; nf++)
            #pragma unroll
            for (int j = 0; j < 4; j++) acc[mf][nf][j] = 0.f;

    const int nchunks = K >> 5;

    // prefetch chunks 0 and 1
    #pragma unroll
    for (int i = 0; i < 8; i++) cp16(sb + soff[i], gsrc[i]);
    cp_commit();
    if (nchunks > 1) {
        #pragma unroll
        for (int i = 0; i < 8; i++)
            cp16(sb + STAGE_BYTES + soff[i], gsrc[i] + 32);
        cp_commit();
    }

    const uint32_t a_r = (uint32_t)(lane & 15);
    const uint32_t a_c = (uint32_t)((lane >> 4) << 3);
    const uint32_t b_r = (uint32_t)(lane & 7);
    const uint32_t b_c = (uint32_t)(((lane >> 3) & 1) << 3);

    int stage = 0, pstage = (nchunks > 1) ? 2 : 1;
    for (int c = 0; c < nchunks; c++) {
        const uint32_t st = sb + (uint32_t)stage * STAGE_BYTES;
        if (c + 2 < nchunks) {
            const uint32_t st2 = sb + (uint32_t)pstage * STAGE_BYTES;
            int k0 = (c + 2) << 5;
            #pragma unroll
            for (int i = 0; i < 8; i++) cp16(st2 + soff[i], gsrc[i] + k0);
            cp_commit();
            cp_wait<2>();
        } else if (c + 1 < nchunks) {
            cp_wait<1>();
        } else {
            cp_wait<0>();
        }
        __syncthreads();

        const uint32_t sAh = st;
        const uint32_t sAl = st + 10240;
        const uint32_t sBh = st + 20480;
        const uint32_t sBl = st + 30720;

        #pragma unroll
        for (int kk = 0; kk < 32; kk += 16) {
            uint32_t ah[4][4], al[4][4], bh[4][2], bl[4][2];
            #pragma unroll
            for (int mf = 0; mf < 4; mf++) {
                uint32_t r = (uint32_t)(warp_m * 64 + mf * 16) + a_r;
                uint32_t o = (r * ROW_ELT + (uint32_t)kk + a_c) * 2;
                ldsm4(ah[mf], sAh + o);
                ldsm4(al[mf], sAl + o);
            }
            #pragma unroll
            for (int nf = 0; nf < 4; nf++) {
                uint32_t r = (uint32_t)(warp_n * 32 + nf * 8) + b_r;
                uint32_t o = (r * ROW_ELT + (uint32_t)kk + b_c) * 2;
                ldsm2(bh[nf], sBh + o);
                ldsm2(bl[nf], sBl + o);
            }
            #pragma unroll
            for (int mf = 0; mf < 4; mf++)
                #pragma unroll
                for (int nf = 0; nf < 4; nf++) {
                    mma_bf16(acc[mf][nf], ah[mf], bh[nf]);
                    mma_bf16(acc[mf][nf], ah[mf], bl[nf]);
                    mma_bf16(acc[mf][nf], al[mf], bh[nf]);
                }
        }
        __syncthreads();

        stage  = (stage  == NSTAGE - 1) ? 0 : stage + 1;
        pstage = (pstage == NSTAGE - 1) ? 0 : pstage + 1;
    }

    #pragma unroll
    for (int nf = 0; nf < 4; nf++) {
        int col = bn + warp_n * 32 + nf * 8 + ((lane & 3) << 1);
        float2 bi = *(const float2*)&bias[col];
        #pragma unroll
        for (int mf = 0; mf < 4; mf++) {
            int row0 = bm + warp_m * 64 + mf * 16 + (lane >> 2);
            float2 o0, o1;
            o0.x = acc[mf][nf][0] + bi.x;
            o0.y = acc[mf][nf][1] + bi.y;
            o1.x = acc[mf][nf][2] + bi.x;
            o1.y = acc[mf][nf][3] + bi.y;
            if (do_relu) {
                o0.x = fmaxf(o0.x, 0.f); o0.y = fmaxf(o0.y, 0.f);
                o1.x = fmaxf(o1.x, 0.f); o1.y = fmaxf(o1.y, 0.f);
            }
            if (Cf) {
                *(float2*)&Cf[(size_t)row0 * N + col]       = o0;
                *(float2*)&Cf[(size_t)(row0 + 8) * N + col] = o1;
            }
            if (Chi) {
                __nv_bfloat16 h0, l0, h1, l1;
                split1(o0.x, h0, l0); split1(o0.y, h1, l1);
                *(__nv_bfloat162*)&Chi[(size_t)row0 * N + col] = __halves2bfloat162(h0, h1);
                *(__nv_bfloat162*)&Clo[(size_t)row0 * N + col] = __halves2bfloat162(l0, l1);
                split1(o1.x, h0, l0); split1(o1.y, h1, l1);
                *(__nv_bfloat162*)&Chi[(size_t)(row0 + 8) * N + col] = __halves2bfloat162(h0, h1);
                *(__nv_bfloat162*)&Clo[(size_t)(row0 + 8) * N + col] = __halves2bfloat162(l0, l1);
            }
        }
    }
}

// ---------- one-shot weight convert + transpose + bias pack (all layers) ----
__global__ void conv_w_all(const float* __restrict__ Wv,  const float* __restrict__ Woff,
                           const float* __restrict__ Wat, const float* __restrict__ Wo,
                           const float* __restrict__ W1,  const float* __restrict__ W2,
                           const float* __restrict__ bv,  const float* __restrict__ boff,
                           const float* __restrict__ bat,
                           __nv_bfloat16* __restrict__ whi,
                           __nv_bfloat16* __restrict__ wlo,
                           float* __restrict__ bvoa)
{
    int idx = blockIdx.x * blockDim.x + threadIdx.x;
    if (idx < NLAY * 640) {
        int l = idx / 640, n = idx - l * 640;
        float b = (n < 256) ? bv[l * 256 + n]
                : (n < 512) ? boff[l * 256 + (n - 256)]
                            : bat[l * 128 + (n - 512)];
        bvoa[idx] = b;
    }
    if (idx >= NLAY * WTOT) return;
    int l = idx / WTOT, r = idx - l * WTOT;
    float v;
    if (r < VOA_SZ) {
        int n = r >> 8, k = r & 255;
        v = (n < 256) ? Wv  [(size_t)l * 65536 + k * 256 + n]
          : (n < 512) ? Woff[(size_t)l * 65536 + k * 256 + (n - 256)]
                      : Wat [(size_t)l * 32768 + k * 128 + (n - 512)];
    } else if (r < W1_OFF) {
        int j = r - WO_OFF; int n = j >> 8, k = j & 255;
        v = Wo[(size_t)l * 65536 + k * 256 + n];
    } else if (r < W2_OFF) {
        int j = r - W1_OFF; int n = j >> 8, k = j & 255;
        v = W1[(size_t)l * 262144 + k * 1024 + n];
    } else {
        int j = r - W2_OFF; int n = j >> 10, k = j & 1023;
        v = W2[(size_t)l * 262144 + k * 256 + n];
    }
    __nv_bfloat16 h, lo;
    split1(v, h, lo);
    whi[idx] = h;
    wlo[idx] = lo;
}

// ---------------- xp = x + pos, fused split (layer 0 only) ----------------
__global__ void add_pos_split(const float* __restrict__ x,
                              const float* __restrict__ pos,
                              float* __restrict__ xp,
                              __nv_bfloat16* __restrict__ hi,
                              __nv_bfloat16* __restrict__ lo, int n4)
{
    int i = blockIdx.x * blockDim.x + threadIdx.x;
    if (i >= n4) return;
    float4 a = ((const float4*)x)[i];
    float4 b = ((const float4*)pos)[i];
    a.x += b.x; a.y += b.y; a.z += b.z; a.w += b.w;
    ((float4*)xp)[i] = a;
    __nv_bfloat16 h0,l0,h1,l1,h2,l2,h3,l3;
    split1(a.x,h0,l0); split1(a.y,h1,l1); split1(a.z,h2,l2); split1(a.w,h3,l3);
    ((__nv_bfloat162*)hi)[2*i]   = __halves2bfloat162(h0,h1);
    ((__nv_bfloat162*)hi)[2*i+1] = __halves2bfloat162(h2,h3);
    ((__nv_bfloat162*)lo)[2*i]   = __halves2bfloat162(l0,l1);
    ((__nv_bfloat162*)lo)[2*i+1] = __halves2bfloat162(l2,l3);
}

// -------- deformable sampling: sample-parallel coords, fused softmax --------
__global__ void deform_sample_kernel(const float* __restrict__ refp,
                                     const float* __restrict__ voa,
                                     __nv_bfloat16* __restrict__ shi,
                                     __nv_bfloat16* __restrict__ slo)
{
    const int gw   = (blockIdx.x * blockDim.x + threadIdx.x) >> 5;
    const int lane = threadIdx.x & 31;
    if (gw >= NROW * NHEAD) return;
    const int row = gw >> 3;
    const int h   = gw & 7;
    const int b   = row / LQ;

    int   off00 = 0, dx = 0, dyv = 0;
    float cw00 = 0.f, cw01 = 0.f, cw10 = 0.f, cw11 = 0.f;
    {
        float lg = (lane < 16) ? voa[(size_t)row * 640 + 512 + h * 16 + lane]
                               : -1e30f;
        float m = lg;
        #pragma unroll
        for (int o = 8; o > 0; o >>= 1)
            m = fmaxf(m, __shfl_xor_sync(0xffffffffu, m, o, 16));
        float e = __expf(lg - m);
        float s = e;
        #pragma unroll
        for (int o = 8; o > 0; o >>= 1)
            s += __shfl_xor_sync(0xffffffffu, s, o, 16);
        float w = e / s;

        if (lane < 16) {
            int l  = lane >> 2;
            int Wl = 128 >> l;
            float wm1 = (float)(Wl - 1);
            float inv = 1.f / (float)Wl;
            const float* offp = voa + (size_t)row * 640 + 256 + h * 32 + lane * 2;
            float ox = offp[0], oy = offp[1];
            float refx = refp[row * 2], refy = refp[row * 2 + 1];
            float xs = (refx + ox * inv) * wm1;
            float ys = (refy + oy * inv) * wm1;
            xs = fminf(fmaxf(xs, 0.f), wm1);
            ys = fminf(fmaxf(ys, 0.f), wm1);
            float x0f = floorf(xs), y0f = floorf(ys);
            float wx = xs - x0f, wy = ys - y0f;
            int x0 = (int)x0f, y0 = (int)y0f;
            int x1 = min(x0 + 1, Wl - 1);
            int y1 = min(y0 + 1, Wl - 1);
            int lvlS = ((l >= 1) ? 16384 : 0) + ((l >= 2) ? 4096 : 0)
                     + ((l >= 3) ? 1024 : 0);
            off00 = (b * LQ + lvlS + y0 * Wl + x0) * 640;
            dx    = (x1 - x0) * 640;
            dyv   = (y1 - y0) * Wl * 640;
            float ax = 1.f - wx, ay = 1.f - wy;
            cw00 = w * ax * ay;
            cw01 = w * wx * ay;
            cw10 = w * ax * wy;
            cw11 = w * wx * wy;
        }
    }

    const float* vw = voa + h * 32 + lane;
    float acc = 0.f;
    #pragma unroll
    for (int s = 0; s < 16; s++) {
        int   o00 = __shfl_sync(0xffffffffu, off00, s);
        int   odx = __shfl_sync(0xffffffffu, dx,    s);
        int   ody = __shfl_sync(0xffffffffu, dyv,   s);
        float c00 = __shfl_sync(0xffffffffu, cw00,  s);
        float c01 = __shfl_sync(0xffffffffu, cw01,  s);
        float c10 = __shfl_sync(0xffffffffu, cw10,  s);
        float c11 = __shfl_sync(0xffffffffu, cw11,  s);
        float p00 = vw[o00];
        float p01 = vw[o00 + odx];
        float p10 = vw[o00 + ody];
        float p11 = vw[o00 + ody + odx];
        acc = fmaf(c00, p00, acc);
        acc = fmaf(c01, p01, acc);
        acc = fmaf(c10, p10, acc);
        acc = fmaf(c11, p11, acc);
    }
    __nv_bfloat16 hh, ll;
    split1(acc, hh, ll);
    shi[(size_t)row * 256 + h * 32 + lane] = hh;
    slo[(size_t)row * 256 + h * 32 + lane] = ll;
}

// -------- fused residual-add + LN, optional (+pos -> xp) and split --------
__global__ void add_ln_kernel(const float* __restrict__ a,
                              const float* __restrict__ b,
                              const float* __restrict__ gamma,
                              const float* __restrict__ beta,
                              float* __restrict__ out,
                              const float* __restrict__ pos,
                              float* __restrict__ xpf,
                              __nv_bfloat16* __restrict__ hi,
                              __nv_bfloat16* __restrict__ lo)
{
    const int warp = (blockIdx.x * blockDim.x + threadIdx.x) >> 5;
    const int lane = threadIdx.x & 31;
    if (warp >= NROW) return;
    const float* pa = a + (size_t)warp * CC;
    const float* pb = b + (size_t)warp * CC;

    float vals[8];
    float sum = 0.f, sq = 0.f;
    #pragma unroll
    for (int j = 0; j < 2; j++) {
        int idx = lane * 4 + j * 128;
        float4 va = *(const float4*)&pa[idx];
        float4 vb = *(const float4*)&pb[idx];
        float t0 = va.x + vb.x, t1 = va.y + vb.y;
        float t2 = va.z + vb.z, t3 = va.w + vb.w;
        vals[j*4+0]=t0; vals[j*4+1]=t1; vals[j*4+2]=t2; vals[j*4+3]=t3;
        sum += t0 + t1 + t2 + t3;
        sq  += t0*t0 + t1*t1 + t2*t2 + t3*t3;
    }
    #pragma unroll
    for (int o = 16; o > 0; o >>= 1) {
        sum += __shfl_xor_sync(0xffffffffu, sum, o);
        sq  += __shfl_xor_sync(0xffffffffu, sq,  o);
    }
    float mean = sum * (1.f / 256.f);
    float var  = sq * (1.f / 256.f) - mean * mean;
    float r    = rsqrtf(var + 1e-5f);

    #pragma unroll
    for (int j = 0; j < 2; j++) {
        int idx = lane * 4 + j * 128;
        size_t p = (size_t)warp * CC + idx;
        float4 g = *(const float4*)&gamma[idx];
        float4 bt = *(const float4*)&beta[idx];
        float4 o;
        o.x = (vals[j*4+0] - mean) * r * g.x + bt.x;
        o.y = (vals[j*4+1] - mean) * r * g.y + bt.y;
        o.z = (vals[j*4+2] - mean) * r * g.z + bt.z;
        o.w = (vals[j*4+3] - mean) * r * g.w + bt.w;
        *(float4*)&out[p] = o;
        float4 sv = o;
        if (xpf) {
            float4 pv = *(const float4*)&pos[p];
            sv.x += pv.x; sv.y += pv.y; sv.z += pv.z; sv.w += pv.w;
            *(float4*)&xpf[p] = sv;
        }
        if (hi) {
            __nv_bfloat16 h0,l0,h1,l1,h2,l2,h3,l3;
            split1(sv.x,h0,l0); split1(sv.y,h1,l1);
            split1(sv.z,h2,l2); split1(sv.w,h3,l3);
            *(__nv_bfloat162*)&hi[p]   = __halves2bfloat162(h0,h1);
            *(__nv_bfloat162*)&hi[p+2] = __halves2bfloat162(h2,h3);
            *(__nv_bfloat162*)&lo[p]   = __halves2bfloat162(l0,l1);
            *(__nv_bfloat162*)&lo[p+2] = __halves2bfloat162(l2,l3);
        }
    }
}

// ---------------- host orchestration ----------------
extern "C" void kernel_launch(void* const* d_in, const int* in_sizes, int n_in,
                              void* d_out, int out_size)
{
    const float* src  = (const float*)d_in[0];
    const float* pos  = (const float*)d_in[1];
    const float* refp = (const float*)d_in[2];
    const float* Woff = (const float*)d_in[3];
    const float* boff = (const float*)d_in[4];
    const float* Wat  = (const float*)d_in[5];
    const float* bat  = (const float*)d_in[6];
    const float* Wv   = (const float*)d_in[7];
    const float* bv   = (const float*)d_in[8];
    const float* Wo   = (const float*)d_in[9];
    const float* bo   = (const float*)d_in[10];
    const float* W1   = (const float*)d_in[11];
    const float* b1   = (const float*)d_in[12];
    const float* W2   = (const float*)d_in[13];
    const float* b2   = (const float*)d_in[14];
    const float* n1s  = (const float*)d_in[15];
    const float* n1b  = (const float*)d_in[16];
    const float* n2s  = (const float*)d_in[17];
    const float* n2b  = (const float*)d_in[18];
    float* x = (float*)d_out;

    float *xp, *voa, *tmp, *bvoa;
    __nv_bfloat16 *ahi, *alo, *bhi, *blo, *whi, *wlo;
    cudaGetSymbolAddress((void**)&xp,   g_xp);
    cudaGetSymbolAddress((void**)&voa,  g_voa);
    cudaGetSymbolAddress((void**)&tmp,  g_tmp);
    cudaGetSymbolAddress((void**)&ahi,  g_ahi);
    cudaGetSymbolAddress((void**)&alo,  g_alo);
    cudaGetSymbolAddress((void**)&bhi,  g_bhi);
    cudaGetSymbolAddress((void**)&blo,  g_blo);
    cudaGetSymbolAddress((void**)&whi,  g_whi);
    cudaGetSymbolAddress((void**)&wlo,  g_wlo);
    cudaGetSymbolAddress((void**)&bvoa, g_bvoa);

    const int GEMM_SMEM = NSTAGE * STAGE_BYTES;   // 122880
    cudaFuncSetAttribute(gemm_bf16x3,
                         cudaFuncAttributeMaxDynamicSharedMemorySize, GEMM_SMEM);

    // one-shot weight conversion for ALL layers
    conv_w_all<<<(NLAY * WTOT + 255) / 256, 256>>>(
        Wv, Woff, Wat, Wo, W1, W2, bv, boff, bat, whi, wlo, bvoa);

    const int MB  = NROW / 128;       // 340
    const int n4c = NROW * CC / 4;

    // layer-0 xp = src + pos (+split); later layers get xp from fused LN2
    add_pos_split<<<(n4c + 255) / 256, 256>>>(src, pos, xp, ahi, alo, n4c);

    for (int i = 0; i < NLAY; i++) {
        const __nv_bfloat16* wh = whi + (size_t)i * WTOT;
        const __nv_bfloat16* wl = wlo + (size_t)i * WTOT;

        // fused v|off|att GEMM  (N=640), A = split(xp)
        gemm_bf16x3<<<dim3(MB, 5), 256, GEMM_SMEM>>>(
            ahi, alo, wh, wl, bvoa + (size_t)i * 640,
            voa, nullptr, nullptr, 256, 640, 0);

        // sampling (fused softmax), emits samp split into ahi/alo
        deform_sample_kernel<<<(NROW * NHEAD * 32) / 256, 256>>>(refp, voa, ahi, alo);

        // attn out proj -> tmp (f32)
        gemm_bf16x3<<<dim3(MB, 2), 256, GEMM_SMEM>>>(
            ahi, alo, wh + WO_OFF, wl + WO_OFF, bo + (size_t)i * CC,
            tmp, nullptr, nullptr, 256, 256, 0);

        // x = LN(xp + attn), split(x) for FFN
        add_ln_kernel<<<(NROW * 32 + 255) / 256, 256>>>(
            xp, tmp, n1s + (size_t)i * CC, n1b + (size_t)i * CC, x,
            nullptr, nullptr, ahi, alo);

        // hidden = relu(x @ W1 + b1), split-only output
        gemm_bf16x3<<<dim3(MB, 8), 256, GEMM_SMEM>>>(
            ahi, alo, wh + W1_OFF, wl + W1_OFF, b1 + (size_t)i * FFD,
            nullptr, bhi, blo, 256, 1024, 1);

        // f = hidden @ W2 + b2 -> tmp (f32)
        gemm_bf16x3<<<dim3(MB, 2), 256, GEMM_SMEM>>>(
            bhi, blo, wh + W2_OFF, wl + W2_OFF, b2 + (size_t)i * CC,
            tmp, nullptr, nullptr, 1024, 256, 0);

        // x = LN(x + f); for layers 0..4 also emit xp = x + pos (+split)
        if (i < NLAY - 1) {
            add_ln_kernel<<<(NROW * 32 + 255) / 256, 256>>>(
                x, tmp, n2s + (size_t)i * CC, n2b + (size_t)i * CC, x,
                pos, xp, ahi, alo);
        } else {
            add_ln_kernel<<<(NROW * 32 + 255) / 256, 256>>>(
                x, tmp, n2s + (size_t)i * CC, n2b + (size_t)i * CC, x,
                nullptr, nullptr, nullptr, nullptr);
        }
    }
}

// round 12
// speedup vs baseline: 1.5269x; 1.5269x over previous
#include <cuda_runtime.h>
#include <cuda_bf16.h>
#include <stdint.h>
#include <math.h>

// Problem constants
#define LQ    21760
#define NB    2
#define CC    256
#define NHEAD 8
#define FFD   1024
#define NLAY  6
#define NROW  (NB*LQ)        // 43520

// packed weight layout per layer (all [N][K] bf16)
#define VOA_SZ   163840      // 640 x 256
#define WO_OFF   163840      // 256 x 256
#define W1_OFF   229376      // 1024 x 256
#define W2_OFF   491520      // 256 x 1024
#define WTOT     753664

// ---------------- device scratch ----------------
__device__ float g_xp  [NROW*CC];        // x + pos (f32, residual for LN1)
__device__ float g_voa [NROW*640];       // [v(256) | off(256) | att(128)]
__device__ float g_tmp [NROW*CC];        // Wo out / W2 out
__device__ __nv_bfloat16 g_ahi[NROW*CC]; // activation split (xp / samp / x)
__device__ __nv_bfloat16 g_alo[NROW*CC];
__device__ __nv_bfloat16 g_bhi[NROW*FFD];// FFN hidden split
__device__ __nv_bfloat16 g_blo[NROW*FFD];
__device__ __nv_bfloat16 g_whi[NLAY*WTOT];
__device__ __nv_bfloat16 g_wlo[NLAY*WTOT];
__device__ float g_bvoa[NLAY*640];       // packed bias for voa GEMM

// ======================= helpers =======================
__device__ __forceinline__ uint32_t smem_u32(const void* p) {
    uint32_t a;
    asm("{ .reg .u64 t; cvta.to.shared.u64 t, %1; cvt.u32.u64 %0, t; }"
        : "=r"(a) : "l"(p));
    return a;
}
__device__ __forceinline__ void cp16(uint32_t dst, const void* src) {
    asm volatile("cp.async.cg.shared.global [%0], [%1], 16;"
                 :: "r"(dst), "l"(src) : "memory");
}
__device__ __forceinline__ void cp_commit() {
    asm volatile("cp.async.commit_group;" ::: "memory");
}
template <int N>
__device__ __forceinline__ void cp_wait() {
    asm volatile("cp.async.wait_group %0;" :: "n"(N) : "memory");
}
__device__ __forceinline__ void ldsm4(uint32_t* r, uint32_t addr) {
    asm volatile("ldmatrix.sync.aligned.m8n8.x4.shared.b16 {%0,%1,%2,%3}, [%4];"
                 : "=r"(r[0]), "=r"(r[1]), "=r"(r[2]), "=r"(r[3]) : "r"(addr));
}
__device__ __forceinline__ void ldsm2(uint32_t* r, uint32_t addr) {
    asm volatile("ldmatrix.sync.aligned.m8n8.x2.shared.b16 {%0,%1}, [%2];"
                 : "=r"(r[0]), "=r"(r[1]) : "r"(addr));
}
__device__ __forceinline__ void mma_bf16(float* c, const uint32_t* a, const uint32_t* b) {
    asm volatile(
        "mma.sync.aligned.m16n8k16.row.col.f32.bf16.bf16.f32 "
        "{%0,%1,%2,%3}, {%4,%5,%6,%7}, {%8,%9}, {%0,%1,%2,%3};"
        : "+f"(c[0]), "+f"(c[1]), "+f"(c[2]), "+f"(c[3])
        : "r"(a[0]), "r"(a[1]), "r"(a[2]), "r"(a[3]), "r"(b[0]), "r"(b[1]));
}
__device__ __forceinline__ void split1(float v, __nv_bfloat16& h, __nv_bfloat16& l) {
    h = __float2bfloat16_rn(v);
    l = __float2bfloat16_rn(v - __bfloat162float(h));
}

// ======================= HMMA GEMM (3-term bf16 split) =======================
// Round-6 body + 3-stage cp.async pipeline.
#define STAGE_BYTES 40960
#define NSTAGE 3
#define ROW_ELT 40

__global__ __launch_bounds__(256)
void gemm_bf16x3(const __nv_bfloat16* __restrict__ Ah,
                 const __nv_bfloat16* __restrict__ Al,
                 const __nv_bfloat16* __restrict__ Bh,
                 const __nv_bfloat16* __restrict__ Bl,
                 const float* __restrict__ bias,
                 float* __restrict__ Cf,
                 __nv_bfloat16* __restrict__ Chi,
                 __nv_bfloat16* __restrict__ Clo,
                 int K, int N, int do_relu)
{
    extern __shared__ __align__(128) char smem[];
    const uint32_t sb = smem_u32(smem);
    const int tid    = threadIdx.x;
    const int lane   = tid & 31;
    const int wid    = tid >> 5;
    const int warp_m = wid >> 2;
    const int warp_n = wid & 3;
    const int bm     = blockIdx.x * 128;
    const int bn     = blockIdx.y * 128;

    const __nv_bfloat16* gsrc[8];
    uint32_t soff[8];
    #pragma unroll
    for (int i = 0; i < 8; i++) {
        int q   = tid + i * 256;
        int arr = q >> 9;
        int rem = q & 511;
        int row = rem >> 2;
        int kc  = (rem & 3) << 3;
        const __nv_bfloat16* base =
            (arr == 0) ? Ah + (size_t)(bm + row) * K :
            (arr == 1) ? Al + (size_t)(bm + row) * K :
            (arr == 2) ? Bh + (size_t)(bn + row) * K :
                         Bl + (size_t)(bn + row) * K;
        gsrc[i] = base + kc;
        soff[i] = (uint32_t)(arr * 10240 + (row * ROW_ELT + kc) * 2);
    }

    float acc[4][4][4];
    #pragma unroll
    for (int mf = 0; mf < 4; mf++)
        #pragma unroll
        for (int nf = 0; nf < 4; nf++)
            #pragma unroll
            for (int j = 0; j < 4; j++) acc[mf][nf][j] = 0.f;

    const int nchunks = K >> 5;

    // prefetch chunks 0 and 1
    #pragma unroll
    for (int i = 0; i < 8; i++) cp16(sb + soff[i], gsrc[i]);
    cp_commit();
    if (nchunks > 1) {
        #pragma unroll
        for (int i = 0; i < 8; i++)
            cp16(sb + STAGE_BYTES + soff[i], gsrc[i] + 32);
        cp_commit();
    }

    const uint32_t a_r = (uint32_t)(lane & 15);
    const uint32_t a_c = (uint32_t)((lane >> 4) << 3);
    const uint32_t b_r = (uint32_t)(lane & 7);
    const uint32_t b_c = (uint32_t)(((lane >> 3) & 1) << 3);

    int stage = 0, pstage = (nchunks > 1) ? 2 : 1;
    for (int c = 0; c < nchunks; c++) {
        const uint32_t st = sb + (uint32_t)stage * STAGE_BYTES;
        if (c + 2 < nchunks) {
            const uint32_t st2 = sb + (uint32_t)pstage * STAGE_BYTES;
            int k0 = (c + 2) << 5;
            #pragma unroll
            for (int i = 0; i < 8; i++) cp16(st2 + soff[i], gsrc[i] + k0);
            cp_commit();
            cp_wait<2>();
        } else if (c + 1 < nchunks) {
            cp_wait<1>();
        } else {
            cp_wait<0>();
        }
        __syncthreads();

        const uint32_t sAh = st;
        const uint32_t sAl = st + 10240;
        const uint32_t sBh = st + 20480;
        const uint32_t sBl = st + 30720;

        #pragma unroll
        for (int kk = 0; kk < 32; kk += 16) {
            uint32_t ah[4][4], al[4][4], bh[4][2], bl[4][2];
            #pragma unroll
            for (int mf = 0; mf < 4; mf++) {
                uint32_t r = (uint32_t)(warp_m * 64 + mf * 16) + a_r;
                uint32_t o = (r * ROW_ELT + (uint32_t)kk + a_c) * 2;
                ldsm4(ah[mf], sAh + o);
                ldsm4(al[mf], sAl + o);
            }
            #pragma unroll
            for (int nf = 0; nf < 4; nf++) {
                uint32_t r = (uint32_t)(warp_n * 32 + nf * 8) + b_r;
                uint32_t o = (r * ROW_ELT + (uint32_t)kk + b_c) * 2;
                ldsm2(bh[nf], sBh + o);
                ldsm2(bl[nf], sBl + o);
            }
            #pragma unroll
            for (int mf = 0; mf < 4; mf++)
                #pragma unroll
                for (int nf = 0; nf < 4; nf++) {
                    mma_bf16(acc[mf][nf], ah[mf], bh[nf]);
                    mma_bf16(acc[mf][nf], ah[mf], bl[nf]);
                    mma_bf16(acc[mf][nf], al[mf], bh[nf]);
                }
        }
        __syncthreads();

        stage  = (stage  == NSTAGE - 1) ? 0 : stage + 1;
        pstage = (pstage == NSTAGE - 1) ? 0 : pstage + 1;
    }

    #pragma unroll
    for (int nf = 0; nf < 4; nf++) {
        int col = bn + warp_n * 32 + nf * 8 + ((lane & 3) << 1);
        float2 bi = *(const float2*)&bias[col];
        #pragma unroll
        for (int mf = 0; mf < 4; mf++) {
            int row0 = bm + warp_m * 64 + mf * 16 + (lane >> 2);
            float2 o0, o1;
            o0.x = acc[mf][nf][0] + bi.x;
            o0.y = acc[mf][nf][1] + bi.y;
            o1.x = acc[mf][nf][2] + bi.x;
            o1.y = acc[mf][nf][3] + bi.y;
            if (do_relu) {
                o0.x = fmaxf(o0.x, 0.f); o0.y = fmaxf(o0.y, 0.f);
                o1.x = fmaxf(o1.x, 0.f); o1.y = fmaxf(o1.y, 0.f);
            }
            if (Cf) {
                *(float2*)&Cf[(size_t)row0 * N + col]       = o0;
                *(float2*)&Cf[(size_t)(row0 + 8) * N + col] = o1;
            }
            if (Chi) {
                __nv_bfloat16 h0, l0, h1, l1;
                split1(o0.x, h0, l0); split1(o0.y, h1, l1);
                *(__nv_bfloat162*)&Chi[(size_t)row0 * N + col] = __halves2bfloat162(h0, h1);
                *(__nv_bfloat162*)&Clo[(size_t)row0 * N + col] = __halves2bfloat162(l0, l1);
                split1(o1.x, h0, l0); split1(o1.y, h1, l1);
                *(__nv_bfloat162*)&Chi[(size_t)(row0 + 8) * N + col] = __halves2bfloat162(h0, h1);
                *(__nv_bfloat162*)&Clo[(size_t)(row0 + 8) * N + col] = __halves2bfloat162(l0, l1);
            }
        }
    }
}

// ---------- one-shot weight convert + transpose + bias pack (all layers) ----
__global__ void conv_w_all(const float* __restrict__ Wv,  const float* __restrict__ Woff,
                           const float* __restrict__ Wat, const float* __restrict__ Wo,
                           const float* __restrict__ W1,  const float* __restrict__ W2,
                           const float* __restrict__ bv,  const float* __restrict__ boff,
                           const float* __restrict__ bat,
                           __nv_bfloat16* __restrict__ whi,
                           __nv_bfloat16* __restrict__ wlo,
                           float* __restrict__ bvoa)
{
    int idx = blockIdx.x * blockDim.x + threadIdx.x;
    if (idx < NLAY * 640) {
        int l = idx / 640, n = idx - l * 640;
        float b = (n < 256) ? bv[l * 256 + n]
                : (n < 512) ? boff[l * 256 + (n - 256)]
                            : bat[l * 128 + (n - 512)];
        bvoa[idx] = b;
    }
    if (idx >= NLAY * WTOT) return;
    int l = idx / WTOT, r = idx - l * WTOT;
    float v;
    if (r < VOA_SZ) {
        int n = r >> 8, k = r & 255;
        v = (n < 256) ? Wv  [(size_t)l * 65536 + k * 256 + n]
          : (n < 512) ? Woff[(size_t)l * 65536 + k * 256 + (n - 256)]
                      : Wat [(size_t)l * 32768 + k * 128 + (n - 512)];
    } else if (r < W1_OFF) {
        int j = r - WO_OFF; int n = j >> 8, k = j & 255;
        v = Wo[(size_t)l * 65536 + k * 256 + n];
    } else if (r < W2_OFF) {
        int j = r - W1_OFF; int n = j >> 8, k = j & 255;
        v = W1[(size_t)l * 262144 + k * 1024 + n];
    } else {
        int j = r - W2_OFF; int n = j >> 10, k = j & 1023;
        v = W2[(size_t)l * 262144 + k * 256 + n];
    }
    __nv_bfloat16 h, lo;
    split1(v, h, lo);
    whi[idx] = h;
    wlo[idx] = lo;
}

// ---------------- xp = x + pos, fused split (layer 0 only) ----------------
__global__ void add_pos_split(const float* __restrict__ x,
                              const float* __restrict__ pos,
                              float* __restrict__ xp,
                              __nv_bfloat16* __restrict__ hi,
                              __nv_bfloat16* __restrict__ lo, int n4)
{
    int i = blockIdx.x * blockDim.x + threadIdx.x;
    if (i >= n4) return;
    float4 a = ((const float4*)x)[i];
    float4 b = ((const float4*)pos)[i];
    a.x += b.x; a.y += b.y; a.z += b.z; a.w += b.w;
    ((float4*)xp)[i] = a;
    __nv_bfloat16 h0,l0,h1,l1,h2,l2,h3,l3;
    split1(a.x,h0,l0); split1(a.y,h1,l1); split1(a.z,h2,l2); split1(a.w,h3,l3);
    ((__nv_bfloat162*)hi)[2*i]   = __halves2bfloat162(h0,h1);
    ((__nv_bfloat162*)hi)[2*i+1] = __halves2bfloat162(h2,h3);
    ((__nv_bfloat162*)lo)[2*i]   = __halves2bfloat162(l0,l1);
    ((__nv_bfloat162*)lo)[2*i+1] = __halves2bfloat162(l2,l3);
}

// -------- deformable sampling: sample-parallel coords, fused softmax --------
__global__ void deform_sample_kernel(const float* __restrict__ refp,
                                     const float* __restrict__ voa,
                                     __nv_bfloat16* __restrict__ shi,
                                     __nv_bfloat16* __restrict__ slo)
{
    const int gw   = (blockIdx.x * blockDim.x + threadIdx.x) >> 5;
    const int lane = threadIdx.x & 31;
    if (gw >= NROW * NHEAD) return;
    const int row = gw >> 3;
    const int h   = gw & 7;
    const int b   = row / LQ;

    int   off00 = 0, dx = 0, dyv = 0;
    float cw00 = 0.f, cw01 = 0.f, cw10 = 0.f, cw11 = 0.f;
    {
        float lg = (lane < 16) ? voa[(size_t)row * 640 + 512 + h * 16 + lane]
                               : -1e30f;
        float m = lg;
        #pragma unroll
        for (int o = 8; o > 0; o >>= 1)
            m = fmaxf(m, __shfl_xor_sync(0xffffffffu, m, o, 16));
        float e = __expf(lg - m);
        float s = e;
        #pragma unroll
        for (int o = 8; o > 0; o >>= 1)
            s += __shfl_xor_sync(0xffffffffu, s, o, 16);
        float w = e / s;

        if (lane < 16) {
            int l  = lane >> 2;
            int Wl = 128 >> l;
            float wm1 = (float)(Wl - 1);
            float inv = 1.f / (float)Wl;
            const float* offp = voa + (size_t)row * 640 + 256 + h * 32 + lane * 2;
            float ox = offp[0], oy = offp[1];
            float refx = refp[row * 2], refy = refp[row * 2 + 1];
            float xs = (refx + ox * inv) * wm1;
            float ys = (refy + oy * inv) * wm1;
            xs = fminf(fmaxf(xs, 0.f), wm1);
            ys = fminf(fmaxf(ys, 0.f), wm1);
            float x0f = floorf(xs), y0f = floorf(ys);
            float wx = xs - x0f, wy = ys - y0f;
            int x0 = (int)x0f, y0 = (int)y0f;
            int x1 = min(x0 + 1, Wl - 1);
            int y1 = min(y0 + 1, Wl - 1);
            int lvlS = ((l >= 1) ? 16384 : 0) + ((l >= 2) ? 4096 : 0)
                     + ((l >= 3) ? 1024 : 0);
            off00 = (b * LQ + lvlS + y0 * Wl + x0) * 640;
            dx    = (x1 - x0) * 640;
            dyv   = (y1 - y0) * Wl * 640;
            float ax = 1.f - wx, ay = 1.f - wy;
            cw00 = w * ax * ay;
            cw01 = w * wx * ay;
            cw10 = w * ax * wy;
            cw11 = w * wx * wy;
        }
    }

    const float* vw = voa + h * 32 + lane;
    float acc = 0.f;
    #pragma unroll
    for (int s = 0; s < 16; s++) {
        int   o00 = __shfl_sync(0xffffffffu, off00, s);
        int   odx = __shfl_sync(0xffffffffu, dx,    s);
        int   ody = __shfl_sync(0xffffffffu, dyv,   s);
        float c00 = __shfl_sync(0xffffffffu, cw00,  s);
        float c01 = __shfl_sync(0xffffffffu, cw01,  s);
        float c10 = __shfl_sync(0xffffffffu, cw10,  s);
        float c11 = __shfl_sync(0xffffffffu, cw11,  s);
        float p00 = vw[o00];
        float p01 = vw[o00 + odx];
        float p10 = vw[o00 + ody];
        float p11 = vw[o00 + ody + odx];
        acc = fmaf(c00, p00, acc);
        acc = fmaf(c01, p01, acc);
        acc = fmaf(c10, p10, acc);
        acc = fmaf(c11, p11, acc);
    }
    __nv_bfloat16 hh, ll;
    split1(acc, hh, ll);
    shi[(size_t)row * 256 + h * 32 + lane] = hh;
    slo[(size_t)row * 256 + h * 32 + lane] = ll;
}

// -------- fused residual-add + LN, optional (+pos -> xp) and split --------
__global__ void add_ln_kernel(const float* __restrict__ a,
                              const float* __restrict__ b,
                              const float* __restrict__ gamma,
                              const float* __restrict__ beta,
                              float* __restrict__ out,
                              const float* __restrict__ pos,
                              float* __restrict__ xpf,
                              __nv_bfloat16* __restrict__ hi,
                              __nv_bfloat16* __restrict__ lo)
{
    const int warp = (blockIdx.x * blockDim.x + threadIdx.x) >> 5;
    const int lane = threadIdx.x & 31;
    if (warp >= NROW) return;
    const float* pa = a + (size_t)warp * CC;
    const float* pb = b + (size_t)warp * CC;

    float vals[8];
    float sum = 0.f, sq = 0.f;
    #pragma unroll
    for (int j = 0; j < 2; j++) {
        int idx = lane * 4 + j * 128;
        float4 va = *(const float4*)&pa[idx];
        float4 vb = *(const float4*)&pb[idx];
        float t0 = va.x + vb.x, t1 = va.y + vb.y;
        float t2 = va.z + vb.z, t3 = va.w + vb.w;
        vals[j*4+0]=t0; vals[j*4+1]=t1; vals[j*4+2]=t2; vals[j*4+3]=t3;
        sum += t0 + t1 + t2 + t3;
        sq  += t0*t0 + t1*t1 + t2*t2 + t3*t3;
    }
    #pragma unroll
    for (int o = 16; o > 0; o >>= 1) {
        sum += __shfl_xor_sync(0xffffffffu, sum, o);
        sq  += __shfl_xor_sync(0xffffffffu, sq,  o);
    }
    float mean = sum * (1.f / 256.f);
    float var  = sq * (1.f / 256.f) - mean * mean;
    float r    = rsqrtf(var + 1e-5f);

    #pragma unroll
    for (int j = 0; j < 2; j++) {
        int idx = lane * 4 + j * 128;
        size_t p = (size_t)warp * CC + idx;
        float4 g = *(const float4*)&gamma[idx];
        float4 bt = *(const float4*)&beta[idx];
        float4 o;
        o.x = (vals[j*4+0] - mean) * r * g.x + bt.x;
        o.y = (vals[j*4+1] - mean) * r * g.y + bt.y;
        o.z = (vals[j*4+2] - mean) * r * g.z + bt.z;
        o.w = (vals[j*4+3] - mean) * r * g.w + bt.w;
        *(float4*)&out[p] = o;
        float4 sv = o;
        if (xpf) {
            float4 pv = *(const float4*)&pos[p];
            sv.x += pv.x; sv.y += pv.y; sv.z += pv.z; sv.w += pv.w;
            *(float4*)&xpf[p] = sv;
        }
        if (hi) {
            __nv_bfloat16 h0,l0,h1,l1,h2,l2,h3,l3;
            split1(sv.x,h0,l0); split1(sv.y,h1,l1);
            split1(sv.z,h2,l2); split1(sv.w,h3,l3);
            *(__nv_bfloat162*)&hi[p]   = __halves2bfloat162(h0,h1);
            *(__nv_bfloat162*)&hi[p+2] = __halves2bfloat162(h2,h3);
            *(__nv_bfloat162*)&lo[p]   = __halves2bfloat162(l0,l1);
            *(__nv_bfloat162*)&lo[p+2] = __halves2bfloat162(l2,l3);
        }
    }
}

// ---------------- host orchestration ----------------
extern "C" void kernel_launch(void* const* d_in, const int* in_sizes, int n_in,
                              void* d_out, int out_size)
{
    const float* src  = (const float*)d_in[0];
    const float* pos  = (const float*)d_in[1];
    const float* refp = (const float*)d_in[2];
    const float* Woff = (const float*)d_in[3];
    const float* boff = (const float*)d_in[4];
    const float* Wat  = (const float*)d_in[5];
    const float* bat  = (const float*)d_in[6];
    const float* Wv   = (const float*)d_in[7];
    const float* bv   = (const float*)d_in[8];
    const float* Wo   = (const float*)d_in[9];
    const float* bo   = (const float*)d_in[10];
    const float* W1   = (const float*)d_in[11];
    const float* b1   = (const float*)d_in[12];
    const float* W2   = (const float*)d_in[13];
    const float* b2   = (const float*)d_in[14];
    const float* n1s  = (const float*)d_in[15];
    const float* n1b  = (const float*)d_in[16];
    const float* n2s  = (const float*)d_in[17];
    const float* n2b  = (const float*)d_in[18];
    float* x = (float*)d_out;

    float *xp, *voa, *tmp, *bvoa;
    __nv_bfloat16 *ahi, *alo, *bhi, *blo, *whi, *wlo;
    cudaGetSymbolAddress((void**)&xp,   g_xp);
    cudaGetSymbolAddress((void**)&voa,  g_voa);
    cudaGetSymbolAddress((void**)&tmp,  g_tmp);
    cudaGetSymbolAddress((void**)&ahi,  g_ahi);
    cudaGetSymbolAddress((void**)&alo,  g_alo);
    cudaGetSymbolAddress((void**)&bhi,  g_bhi);
    cudaGetSymbolAddress((void**)&blo,  g_blo);
    cudaGetSymbolAddress((void**)&whi,  g_whi);
    cudaGetSymbolAddress((void**)&wlo,  g_wlo);
    cudaGetSymbolAddress((void**)&bvoa, g_bvoa);

    const int GEMM_SMEM = NSTAGE * STAGE_BYTES;   // 122880
    cudaFuncSetAttribute(gemm_bf16x3,
                         cudaFuncAttributeMaxDynamicSharedMemorySize, GEMM_SMEM);

    // one-shot weight conversion for ALL layers
    conv_w_all<<<(NLAY * WTOT + 255) / 256, 256>>>(
        Wv, Woff, Wat, Wo, W1, W2, bv, boff, bat, whi, wlo, bvoa);

    const int MB  = NROW / 128;       // 340
    const int n4c = NROW * CC / 4;

    // layer-0 xp = src + pos (+split); later layers get xp from fused LN2
    add_pos_split<<<(n4c + 255) / 256, 256>>>(src, pos, xp, ahi, alo, n4c);

    for (int i = 0; i < NLAY; i++) {
        const __nv_bfloat16* wh = whi + (size_t)i * WTOT;
        const __nv_bfloat16* wl = wlo + (size_t)i * WTOT;

        // fused v|off|att GEMM  (N=640), A = split(xp)
        gemm_bf16x3<<<dim3(MB, 5), 256, GEMM_SMEM>>>(
            ahi, alo, wh, wl, bvoa + (size_t)i * 640,
            voa, nullptr, nullptr, 256, 640, 0);

        // sampling (fused softmax), emits samp split into ahi/alo
        deform_sample_kernel<<<(NROW * NHEAD * 32) / 256, 256>>>(refp, voa, ahi, alo);

        // attn out proj -> tmp (f32)
        gemm_bf16x3<<<dim3(MB, 2), 256, GEMM_SMEM>>>(
            ahi, alo, wh + WO_OFF, wl + WO_OFF, bo + (size_t)i * CC,
            tmp, nullptr, nullptr, 256, 256, 0);

        // x = LN(xp + attn), split(x) for FFN
        add_ln_kernel<<<(NROW * 32 + 255) / 256, 256>>>(
            xp, tmp, n1s + (size_t)i * CC, n1b + (size_t)i * CC, x,
            nullptr, nullptr, ahi, alo);

        // hidden = relu(x @ W1 + b1), split-only output
        gemm_bf16x3<<<dim3(MB, 8), 256, GEMM_SMEM>>>(
            ahi, alo, wh + W1_OFF, wl + W1_OFF, b1 + (size_t)i * FFD,
            nullptr, bhi, blo, 256, 1024, 1);

        // f = hidden @ W2 + b2 -> tmp (f32)
        gemm_bf16x3<<<dim3(MB, 2), 256, GEMM_SMEM>>>(
            bhi, blo, wh + W2_OFF, wl + W2_OFF, b2 + (size_t)i * CC,
            tmp, nullptr, nullptr, 1024, 256, 0);

        // x = LN(x + f); for layers 0..4 also emit xp = x + pos (+split)
        if (i < NLAY - 1) {
            add_ln_kernel<<<(NROW * 32 + 255) / 256, 256>>>(
                x, tmp, n2s + (size_t)i * CC, n2b + (size_t)i * CC, x,
                pos, xp, ahi, alo);
        } else {
            add_ln_kernel<<<(NROW * 32 + 255) / 256, 256>>>(
                x, tmp, n2s + (size_t)i * CC, n2b + (size_t)i * CC, x,
                nullptr, nullptr, nullptr, nullptr);
        }
    }
}

// round 15
// speedup vs baseline: 1.5569x; 1.0196x over previous
#include <cuda_runtime.h>
#include <cuda_bf16.h>
#include <stdint.h>
#include <math.h>

// Problem constants
#define LQ    21760
#define NB    2
#define CC    256
#define NHEAD 8
#define FFD   1024
#define NLAY  6
#define NROW  (NB*LQ)        // 43520

// packed weight layout per layer (all [N][K] bf16)
#define VOA_SZ   163840      // 640 x 256
#define WO_OFF   163840      // 256 x 256
#define W1_OFF   229376      // 1024 x 256
#define W2_OFF   491520      // 256 x 1024
#define WTOT     753664

// ---------------- device scratch ----------------
__device__ float g_xp  [NROW*CC];        // x + pos (f32, residual for LN1)
__device__ float g_voa [NROW*640];       // [v(256) | off(256) | att(128)]
__device__ float g_tmp [NROW*CC];        // Wo out / W2 out
__device__ __nv_bfloat16 g_ahi[NROW*CC]; // activation split (xp / samp / x)
__device__ __nv_bfloat16 g_alo[NROW*CC];
__device__ __nv_bfloat16 g_bhi[NROW*FFD];// FFN hidden split
__device__ __nv_bfloat16 g_blo[NROW*FFD];
__device__ __nv_bfloat16 g_whi[NLAY*WTOT];
__device__ __nv_bfloat16 g_wlo[NLAY*WTOT];
__device__ float g_bvoa[NLAY*640];       // packed bias for voa GEMM

// ======================= helpers =======================
__device__ __forceinline__ uint32_t smem_u32(const void* p) {
    uint32_t a;
    asm("{ .reg .u64 t; cvta.to.shared.u64 t, %1; cvt.u32.u64 %0, t; }"
        : "=r"(a) : "l"(p));
    return a;
}
__device__ __forceinline__ void cp16(uint32_t dst, const void* src) {
    asm volatile("cp.async.cg.shared.global [%0], [%1], 16;"
                 :: "r"(dst), "l"(src) : "memory");
}
__device__ __forceinline__ void cp_commit() {
    asm volatile("cp.async.commit_group;" ::: "memory");
}
template <int N>
__device__ __forceinline__ void cp_wait() {
    asm volatile("cp.async.wait_group %0;" :: "n"(N) : "memory");
}
__device__ __forceinline__ void ldsm4(uint32_t* r, uint32_t addr) {
    asm volatile("ldmatrix.sync.aligned.m8n8.x4.shared.b16 {%0,%1,%2,%3}, [%4];"
                 : "=r"(r[0]), "=r"(r[1]), "=r"(r[2]), "=r"(r[3]) : "r"(addr));
}
__device__ __forceinline__ void mma_bf16(float* c, const uint32_t* a, const uint32_t* b) {
    asm volatile(
        "mma.sync.aligned.m16n8k16.row.col.f32.bf16.bf16.f32 "
        "{%0,%1,%2,%3}, {%4,%5,%6,%7}, {%8,%9}, {%0,%1,%2,%3};"
        : "+f"(c[0]), "+f"(c[1]), "+f"(c[2]), "+f"(c[3])
        : "r"(a[0]), "r"(a[1]), "r"(a[2]), "r"(a[3]), "r"(b[0]), "r"(b[1]));
}
__device__ __forceinline__ void split1(float v, __nv_bfloat16& h, __nv_bfloat16& l) {
    h = __float2bfloat16_rn(v);
    l = __float2bfloat16_rn(v - __bfloat162float(h));
}

// ======================= HMMA GEMM (3-term bf16 split) =======================
// Round-6 structure: 128x128 tile, BK=32, double-buffered cp.async,
// compile-time stage alternation. Single change vs round-6: B fragments
// loaded with paired ldsm4 (verified mapping, round 7) instead of 8x ldsm2.
#define STAGE_BYTES 40960
#define ROW_ELT 40

__global__ __launch_bounds__(256)
void gemm_bf16x3(const __nv_bfloat16* __restrict__ Ah,
                 const __nv_bfloat16* __restrict__ Al,
                 const __nv_bfloat16* __restrict__ Bh,
                 const __nv_bfloat16* __restrict__ Bl,
                 const float* __restrict__ bias,
                 float* __restrict__ Cf,
                 __nv_bfloat16* __restrict__ Chi,
                 __nv_bfloat16* __restrict__ Clo,
                 int K, int N, int do_relu)
{
    extern __shared__ __align__(128) char smem[];
    const uint32_t sb = smem_u32(smem);
    const int tid    = threadIdx.x;
    const int lane   = tid & 31;
    const int wid    = tid >> 5;
    const int warp_m = wid >> 2;
    const int warp_n = wid & 3;
    const int bm     = blockIdx.x * 128;
    const int bn     = blockIdx.y * 128;

    const __nv_bfloat16* gsrc[8];
    uint32_t soff[8];
    #pragma unroll
    for (int i = 0; i < 8; i++) {
        int q   = tid + i * 256;
        int arr = q >> 9;
        int rem = q & 511;
        int row = rem >> 2;
        int kc  = (rem & 3) << 3;
        const __nv_bfloat16* base =
            (arr == 0) ? Ah + (size_t)(bm + row) * K :
            (arr == 1) ? Al + (size_t)(bm + row) * K :
            (arr == 2) ? Bh + (size_t)(bn + row) * K :
                         Bl + (size_t)(bn + row) * K;
        gsrc[i] = base + kc;
        soff[i] = (uint32_t)(arr * 10240 + (row * ROW_ELT + kc) * 2);
    }

    float acc[4][4][4];
    #pragma unroll
    for (int mf = 0; mf < 4; mf++)
        #pragma unroll
        for (int nf = 0; nf < 4; nf++)
            #pragma unroll
            for (int j = 0; j < 4; j++) acc[mf][nf][j] = 0.f;

    const int nchunks = K >> 5;
    #pragma unroll
    for (int i = 0; i < 8; i++) cp16(sb + soff[i], gsrc[i]);
    cp_commit();

    // ldmatrix lane addressing
    const uint32_t a_r = (uint32_t)(lane & 15);          // A rows m0..15
    const uint32_t a_c = (uint32_t)((lane >> 4) << 3);   // A k 0/+8
    const uint32_t b_r = (uint32_t)(lane & 15);          // B rows n0..15
    const uint32_t b_c = (uint32_t)((lane >> 4) << 3);   // B k 0/+8

    for (int c = 0; c < nchunks; c++) {
        const uint32_t st = sb + (uint32_t)(c & 1) * STAGE_BYTES;
        if (c + 1 < nchunks) {
            const uint32_t st2 = sb + (uint32_t)((c + 1) & 1) * STAGE_BYTES;
            int k0 = (c + 1) << 5;
            #pragma unroll
            for (int i = 0; i < 8; i++) cp16(st2 + soff[i], gsrc[i] + k0);
            cp_commit();
            cp_wait<1>();
        } else {
            cp_wait<0>();
        }
        __syncthreads();

        const uint32_t sAh = st;
        const uint32_t sAl = st + 10240;
        const uint32_t sBh = st + 20480;
        const uint32_t sBl = st + 30720;

        #pragma unroll
        for (int kk = 0; kk < 32; kk += 16) {
            uint32_t ah[4][4], al[4][4], bh[4][2], bl[4][2];
            #pragma unroll
            for (int mf = 0; mf < 4; mf++) {
                uint32_t r = (uint32_t)(warp_m * 64 + mf * 16) + a_r;
                uint32_t o = (r * ROW_ELT + (uint32_t)kk) * 2 + a_c * 2;
                ldsm4(ah[mf], sAh + o);
                ldsm4(al[mf], sAl + o);
            }
            #pragma unroll
            for (int np = 0; np < 2; np++) {
                uint32_t r = (uint32_t)(warp_n * 32 + np * 16) + b_r;
                uint32_t o = (r * ROW_ELT + (uint32_t)kk) * 2 + b_c * 2;
                uint32_t t[4];
                ldsm4(t, sBh + o);
                bh[2*np][0]   = t[0]; bh[2*np+1][0] = t[1];
                bh[2*np][1]   = t[2]; bh[2*np+1][1] = t[3];
                ldsm4(t, sBl + o);
                bl[2*np][0]   = t[0]; bl[2*np+1][0] = t[1];
                bl[2*np][1]   = t[2]; bl[2*np+1][1] = t[3];
            }
            #pragma unroll
            for (int mf = 0; mf < 4; mf++)
                #pragma unroll
                for (int nf = 0; nf < 4; nf++) {
                    mma_bf16(acc[mf][nf], ah[mf], bh[nf]);
                    mma_bf16(acc[mf][nf], ah[mf], bl[nf]);
                    mma_bf16(acc[mf][nf], al[mf], bh[nf]);
                }
        }
        __syncthreads();
    }

    #pragma unroll
    for (int nf = 0; nf < 4; nf++) {
        int col = bn + warp_n * 32 + nf * 8 + ((lane & 3) << 1);
        float2 bi = *(const float2*)&bias[col];
        #pragma unroll
        for (int mf = 0; mf < 4; mf++) {
            int row0 = bm + warp_m * 64 + mf * 16 + (lane >> 2);
            float2 o0, o1;
            o0.x = acc[mf][nf][0] + bi.x;
            o0.y = acc[mf][nf][1] + bi.y;
            o1.x = acc[mf][nf][2] + bi.x;
            o1.y = acc[mf][nf][3] + bi.y;
            if (do_relu) {
                o0.x = fmaxf(o0.x, 0.f); o0.y = fmaxf(o0.y, 0.f);
                o1.x = fmaxf(o1.x, 0.f); o1.y = fmaxf(o1.y, 0.f);
            }
            if (Cf) {
                *(float2*)&Cf[(size_t)row0 * N + col]       = o0;
                *(float2*)&Cf[(size_t)(row0 + 8) * N + col] = o1;
            }
            if (Chi) {
                __nv_bfloat16 h0, l0, h1, l1;
                split1(o0.x, h0, l0); split1(o0.y, h1, l1);
                *(__nv_bfloat162*)&Chi[(size_t)row0 * N + col] = __halves2bfloat162(h0, h1);
                *(__nv_bfloat162*)&Clo[(size_t)row0 * N + col] = __halves2bfloat162(l0, l1);
                split1(o1.x, h0, l0); split1(o1.y, h1, l1);
                *(__nv_bfloat162*)&Chi[(size_t)(row0 + 8) * N + col] = __halves2bfloat162(h0, h1);
                *(__nv_bfloat162*)&Clo[(size_t)(row0 + 8) * N + col] = __halves2bfloat162(l0, l1);
            }
        }
    }
}

// ---------- one-shot weight convert + transpose + bias pack (all layers) ----
__global__ void conv_w_all(const float* __restrict__ Wv,  const float* __restrict__ Woff,
                           const float* __restrict__ Wat, const float* __restrict__ Wo,
                           const float* __restrict__ W1,  const float* __restrict__ W2,
                           const float* __restrict__ bv,  const float* __restrict__ boff,
                           const float* __restrict__ bat,
                           __nv_bfloat16* __restrict__ whi,
                           __nv_bfloat16* __restrict__ wlo,
                           float* __restrict__ bvoa)
{
    int idx = blockIdx.x * blockDim.x + threadIdx.x;
    if (idx < NLAY * 640) {
        int l = idx / 640, n = idx - l * 640;
        float b = (n < 256) ? bv[l * 256 + n]
                : (n < 512) ? boff[l * 256 + (n - 256)]
                            : bat[l * 128 + (n - 512)];
        bvoa[idx] = b;
    }
    if (idx >= NLAY * WTOT) return;
    int l = idx / WTOT, r = idx - l * WTOT;
    float v;
    if (r < VOA_SZ) {
        int n = r >> 8, k = r & 255;
        v = (n < 256) ? Wv  [(size_t)l * 65536 + k * 256 + n]
          : (n < 512) ? Woff[(size_t)l * 65536 + k * 256 + (n - 256)]
                      : Wat [(size_t)l * 32768 + k * 128 + (n - 512)];
    } else if (r < W1_OFF) {
        int j = r - WO_OFF; int n = j >> 8, k = j & 255;
        v = Wo[(size_t)l * 65536 + k * 256 + n];
    } else if (r < W2_OFF) {
        int j = r - W1_OFF; int n = j >> 8, k = j & 255;
        v = W1[(size_t)l * 262144 + k * 1024 + n];
    } else {
        int j = r - W2_OFF; int n = j >> 10, k = j & 1023;
        v = W2[(size_t)l * 262144 + k * 256 + n];
    }
    __nv_bfloat16 h, lo;
    split1(v, h, lo);
    whi[idx] = h;
    wlo[idx] = lo;
}

// ---------------- xp = x + pos, fused split (layer 0 only) ----------------
__global__ void add_pos_split(const float* __restrict__ x,
                              const float* __restrict__ pos,
                              float* __restrict__ xp,
                              __nv_bfloat16* __restrict__ hi,
                              __nv_bfloat16* __restrict__ lo, int n4)
{
    int i = blockIdx.x * blockDim.x + threadIdx.x;
    if (i >= n4) return;
    float4 a = ((const float4*)x)[i];
    float4 b = ((const float4*)pos)[i];
    a.x += b.x; a.y += b.y; a.z += b.z; a.w += b.w;
    ((float4*)xp)[i] = a;
    __nv_bfloat16 h0,l0,h1,l1,h2,l2,h3,l3;
    split1(a.x,h0,l0); split1(a.y,h1,l1); split1(a.z,h2,l2); split1(a.w,h3,l3);
    ((__nv_bfloat162*)hi)[2*i]   = __halves2bfloat162(h0,h1);
    ((__nv_bfloat162*)hi)[2*i+1] = __halves2bfloat162(h2,h3);
    ((__nv_bfloat162*)lo)[2*i]   = __halves2bfloat162(l0,l1);
    ((__nv_bfloat162*)lo)[2*i+1] = __halves2bfloat162(l2,l3);
}

// -------- deformable sampling: sample-parallel coords, fused softmax --------
__global__ void deform_sample_kernel(const float* __restrict__ refp,
                                     const float* __restrict__ voa,
                                     __nv_bfloat16* __restrict__ shi,
                                     __nv_bfloat16* __restrict__ slo)
{
    const int gw   = (blockIdx.x * blockDim.x + threadIdx.x) >> 5;
    const int lane = threadIdx.x & 31;
    if (gw >= NROW * NHEAD) return;
    const int row = gw >> 3;
    const int h   = gw & 7;
    const int b   = row / LQ;

    int   off00 = 0, dx = 0, dyv = 0;
    float cw00 = 0.f, cw01 = 0.f, cw10 = 0.f, cw11 = 0.f;
    {
        float lg = (lane < 16) ? voa[(size_t)row * 640 + 512 + h * 16 + lane]
                               : -1e30f;
        float m = lg;
        #pragma unroll
        for (int o = 8; o > 0; o >>= 1)
            m = fmaxf(m, __shfl_xor_sync(0xffffffffu, m, o, 16));
        float e = __expf(lg - m);
        float s = e;
        #pragma unroll
        for (int o = 8; o > 0; o >>= 1)
            s += __shfl_xor_sync(0xffffffffu, s, o, 16);
        float w = e / s;

        if (lane < 16) {
            int l  = lane >> 2;
            int Wl = 128 >> l;
            float wm1 = (float)(Wl - 1);
            float inv = 1.f / (float)Wl;
            const float* offp = voa + (size_t)row * 640 + 256 + h * 32 + lane * 2;
            float ox = offp[0], oy = offp[1];
            float refx = refp[row * 2], refy = refp[row * 2 + 1];
            float xs = (refx + ox * inv) * wm1;
            float ys = (refy + oy * inv) * wm1;
            xs = fminf(fmaxf(xs, 0.f), wm1);
            ys = fminf(fmaxf(ys, 0.f), wm1);
            float x0f = floorf(xs), y0f = floorf(ys);
            float wx = xs - x0f, wy = ys - y0f;
            int x0 = (int)x0f, y0 = (int)y0f;
            int x1 = min(x0 + 1, Wl - 1);
            int y1 = min(y0 + 1, Wl - 1);
            int lvlS = ((l >= 1) ? 16384 : 0) + ((l >= 2) ? 4096 : 0)
                     + ((l >= 3) ? 1024 : 0);
            off00 = (b * LQ + lvlS + y0 * Wl + x0) * 640;
            dx    = (x1 - x0) * 640;
            dyv   = (y1 - y0) * Wl * 640;
            float ax = 1.f - wx, ay = 1.f - wy;
            cw00 = w * ax * ay;
            cw01 = w * wx * ay;
            cw10 = w * ax * wy;
            cw11 = w * wx * wy;
        }
    }

    const float* vw = voa + h * 32 + lane;
    float acc = 0.f;
    #pragma unroll
    for (int s = 0; s < 16; s++) {
        int   o00 = __shfl_sync(0xffffffffu, off00, s);
        int   odx = __shfl_sync(0xffffffffu, dx,    s);
        int   ody = __shfl_sync(0xffffffffu, dyv,   s);
        float c00 = __shfl_sync(0xffffffffu, cw00,  s);
        float c01 = __shfl_sync(0xffffffffu, cw01,  s);
        float c10 = __shfl_sync(0xffffffffu, cw10,  s);
        float c11 = __shfl_sync(0xffffffffu, cw11,  s);
        float p00 = vw[o00];
        float p01 = vw[o00 + odx];
        float p10 = vw[o00 + ody];
        float p11 = vw[o00 + ody + odx];
        acc = fmaf(c00, p00, acc);
        acc = fmaf(c01, p01, acc);
        acc = fmaf(c10, p10, acc);
        acc = fmaf(c11, p11, acc);
    }
    __nv_bfloat16 hh, ll;
    split1(acc, hh, ll);
    shi[(size_t)row * 256 + h * 32 + lane] = hh;
    slo[(size_t)row * 256 + h * 32 + lane] = ll;
}

// -------- fused residual-add + LN, optional (+pos -> xp) and split --------
__global__ void add_ln_kernel(const float* __restrict__ a,
                              const float* __restrict__ b,
                              const float* __restrict__ gamma,
                              const float* __restrict__ beta,
                              float* __restrict__ out,
                              const float* __restrict__ pos,
                              float* __restrict__ xpf,
                              __nv_bfloat16* __restrict__ hi,
                              __nv_bfloat16* __restrict__ lo)
{
    const int warp = (blockIdx.x * blockDim.x + threadIdx.x) >> 5;
    const int lane = threadIdx.x & 31;
    if (warp >= NROW) return;
    const float* pa = a + (size_t)warp * CC;
    const float* pb = b + (size_t)warp * CC;

    float vals[8];
    float sum = 0.f, sq = 0.f;
    #pragma unroll
    for (int j = 0; j < 2; j++) {
        int idx = lane * 4 + j * 128;
        float4 va = *(const float4*)&pa[idx];
        float4 vb = *(const float4*)&pb[idx];
        float t0 = va.x + vb.x, t1 = va.y + vb.y;
        float t2 = va.z + vb.z, t3 = va.w + vb.w;
        vals[j*4+0]=t0; vals[j*4+1]=t1; vals[j*4+2]=t2; vals[j*4+3]=t3;
        sum += t0 + t1 + t2 + t3;
        sq  += t0*t0 + t1*t1 + t2*t2 + t3*t3;
    }
    #pragma unroll
    for (int o = 16; o > 0; o >>= 1) {
        sum += __shfl_xor_sync(0xffffffffu, sum, o);
        sq  += __shfl_xor_sync(0xffffffffu, sq,  o);
    }
    float mean = sum * (1.f / 256.f);
    float var  = sq * (1.f / 256.f) - mean * mean;
    float r    = rsqrtf(var + 1e-5f);

    #pragma unroll
    for (int j = 0; j < 2; j++) {
        int idx = lane * 4 + j * 128;
        size_t p = (size_t)warp * CC + idx;
        float4 g = *(const float4*)&gamma[idx];
        float4 bt = *(const float4*)&beta[idx];
        float4 o;
        o.x = (vals[j*4+0] - mean) * r * g.x + bt.x;
        o.y = (vals[j*4+1] - mean) * r * g.y + bt.y;
        o.z = (vals[j*4+2] - mean) * r * g.z + bt.z;
        o.w = (vals[j*4+3] - mean) * r * g.w + bt.w;
        *(float4*)&out[p] = o;
        float4 sv = o;
        if (xpf) {
            float4 pv = *(const float4*)&pos[p];
            sv.x += pv.x; sv.y += pv.y; sv.z += pv.z; sv.w += pv.w;
            *(float4*)&xpf[p] = sv;
        }
        if (hi) {
            __nv_bfloat16 h0,l0,h1,l1,h2,l2,h3,l3;
            split1(sv.x,h0,l0); split1(sv.y,h1,l1);
            split1(sv.z,h2,l2); split1(sv.w,h3,l3);
            *(__nv_bfloat162*)&hi[p]   = __halves2bfloat162(h0,h1);
            *(__nv_bfloat162*)&hi[p+2] = __halves2bfloat162(h2,h3);
            *(__nv_bfloat162*)&lo[p]   = __halves2bfloat162(l0,l1);
            *(__nv_bfloat162*)&lo[p+2] = __halves2bfloat162(l2,l3);
        }
    }
}

// ---------------- host orchestration ----------------
extern "C" void kernel_launch(void* const* d_in, const int* in_sizes, int n_in,
                              void* d_out, int out_size)
{
    const float* src  = (const float*)d_in[0];
    const float* pos  = (const float*)d_in[1];
    const float* refp = (const float*)d_in[2];
    const float* Woff = (const float*)d_in[3];
    const float* boff = (const float*)d_in[4];
    const float* Wat  = (const float*)d_in[5];
    const float* bat  = (const float*)d_in[6];
    const float* Wv   = (const float*)d_in[7];
    const float* bv   = (const float*)d_in[8];
    const float* Wo   = (const float*)d_in[9];
    const float* bo   = (const float*)d_in[10];
    const float* W1   = (const float*)d_in[11];
    const float* b1   = (const float*)d_in[12];
    const float* W2   = (const float*)d_in[13];
    const float* b2   = (const float*)d_in[14];
    const float* n1s  = (const float*)d_in[15];
    const float* n1b  = (const float*)d_in[16];
    const float* n2s  = (const float*)d_in[17];
    const float* n2b  = (const float*)d_in[18];
    float* x = (float*)d_out;

    float *xp, *voa, *tmp, *bvoa;
    __nv_bfloat16 *ahi, *alo, *bhi, *blo, *whi, *wlo;
    cudaGetSymbolAddress((void**)&xp,   g_xp);
    cudaGetSymbolAddress((void**)&voa,  g_voa);
    cudaGetSymbolAddress((void**)&tmp,  g_tmp);
    cudaGetSymbolAddress((void**)&ahi,  g_ahi);
    cudaGetSymbolAddress((void**)&alo,  g_alo);
    cudaGetSymbolAddress((void**)&bhi,  g_bhi);
    cudaGetSymbolAddress((void**)&blo,  g_blo);
    cudaGetSymbolAddress((void**)&whi,  g_whi);
    cudaGetSymbolAddress((void**)&wlo,  g_wlo);
    cudaGetSymbolAddress((void**)&bvoa, g_bvoa);

    const int GEMM_SMEM = 2 * STAGE_BYTES;   // 81920
    cudaFuncSetAttribute(gemm_bf16x3,
                         cudaFuncAttributeMaxDynamicSharedMemorySize, GEMM_SMEM);

    // one-shot weight conversion for ALL layers
    conv_w_all<<<(NLAY * WTOT + 255) / 256, 256>>>(
        Wv, Woff, Wat, Wo, W1, W2, bv, boff, bat, whi, wlo, bvoa);

    const int MB  = NROW / 128;       // 340
    const int n4c = NROW * CC / 4;

    // layer-0 xp = src + pos (+split); later layers get xp from fused LN2
    add_pos_split<<<(n4c + 255) / 256, 256>>>(src, pos, xp, ahi, alo, n4c);

    for (int i = 0; i < NLAY; i++) {
        const __nv_bfloat16* wh = whi + (size_t)i * WTOT;
        const __nv_bfloat16* wl = wlo + (size_t)i * WTOT;

        // fused v|off|att GEMM  (N=640), A = split(xp)
        gemm_bf16x3<<<dim3(MB, 5), 256, GEMM_SMEM>>>(
            ahi, alo, wh, wl, bvoa + (size_t)i * 640,
            voa, nullptr, nullptr, 256, 640, 0);

        // sampling (fused softmax), emits samp split into ahi/alo
        deform_sample_kernel<<<(NROW * NHEAD * 32) / 256, 256>>>(refp, voa, ahi, alo);

        // attn out proj -> tmp (f32)
        gemm_bf16x3<<<dim3(MB, 2), 256, GEMM_SMEM>>>(
            ahi, alo, wh + WO_OFF, wl + WO_OFF, bo + (size_t)i * CC,
            tmp, nullptr, nullptr, 256, 256, 0);

        // x = LN(xp + attn), split(x) for FFN
        add_ln_kernel<<<(NROW * 32 + 255) / 256, 256>>>(
            xp, tmp, n1s + (size_t)i * CC, n1b + (size_t)i * CC, x,
            nullptr, nullptr, ahi, alo);

        // hidden = relu(x @ W1 + b1), split-only output
        gemm_bf16x3<<<dim3(MB, 8), 256, GEMM_SMEM>>>(
            ahi, alo, wh + W1_OFF, wl + W1_OFF, b1 + (size_t)i * FFD,
            nullptr, bhi, blo, 256, 1024, 1);

        // f = hidden @ W2 + b2 -> tmp (f32)
        gemm_bf16x3<<<dim3(MB, 2), 256, GEMM_SMEM>>>(
            bhi, blo, wh + W2_OFF, wl + W2_OFF, b2 + (size_t)i * CC,
            tmp, nullptr, nullptr, 1024, 256, 0);

        // x = LN(x + f); for layers 0..4 also emit xp = x + pos (+split)
        if (i < NLAY - 1) {
            add_ln_kernel<<<(NROW * 32 + 255) / 256, 256>>>(
                x, tmp, n2s + (size_t)i * CC, n2b + (size_t)i * CC, x,
                pos, xp, ahi, alo);
        } else {
            add_ln_kernel<<<(NROW * 32 + 255) / 256, 256>>>(
                x, tmp, n2s + (size_t)i * CC, n2b + (size_t)i * CC, x,
                nullptr, nullptr, nullptr, nullptr);
        }
    }
}

// round 16
// speedup vs baseline: 1.7317x; 1.1123x over previous
#include <cuda_runtime.h>
#include <cuda_bf16.h>
#include <stdint.h>
#include <math.h>

// Problem constants
#define LQ    21760
#define NB    2
#define CC    256
#define NHEAD 8
#define FFD   1024
#define NLAY  6
#define NROW  (NB*LQ)        // 43520

// packed weight layout per layer (all [N][K] bf16)
#define VOA_SZ   163840      // 640 x 256
#define WO_OFF   163840      // 256 x 256
#define W1_OFF   229376      // 1024 x 256
#define W2_OFF   491520      // 256 x 1024
#define WTOT     753664

// ---------------- device scratch ----------------
__device__ float g_xp  [NROW*CC];        // x + pos (f32, residual for LN1)
__device__ float g_voa [NROW*640];       // [v(256) | off(256) | att(128)]
__device__ float g_tmp [NROW*CC];        // Wo out / W2 out
__device__ __nv_bfloat16 g_vb [NROW*CC]; // bf16 copy of v channels (gather src)
__device__ __nv_bfloat16 g_ahi[NROW*CC]; // activation split (xp / samp / x)
__device__ __nv_bfloat16 g_alo[NROW*CC];
__device__ __nv_bfloat16 g_bhi[NROW*FFD];// FFN hidden split
__device__ __nv_bfloat16 g_blo[NROW*FFD];
__device__ __nv_bfloat16 g_whi[NLAY*WTOT];
__device__ __nv_bfloat16 g_wlo[NLAY*WTOT];
__device__ float g_bvoa[NLAY*640];       // packed bias for voa GEMM

// ======================= helpers =======================
__device__ __forceinline__ uint32_t smem_u32(const void* p) {
    uint32_t a;
    asm("{ .reg .u64 t; cvta.to.shared.u64 t, %1; cvt.u32.u64 %0, t; }"
        : "=r"(a) : "l"(p));
    return a;
}
__device__ __forceinline__ void cp16(uint32_t dst, const void* src) {
    asm volatile("cp.async.cg.shared.global [%0], [%1], 16;"
                 :: "r"(dst), "l"(src) : "memory");
}
__device__ __forceinline__ void cp_commit() {
    asm volatile("cp.async.commit_group;" ::: "memory");
}
template <int N>
__device__ __forceinline__ void cp_wait() {
    asm volatile("cp.async.wait_group %0;" :: "n"(N) : "memory");
}
__device__ __forceinline__ void ldsm4(uint32_t* r, uint32_t addr) {
    asm volatile("ldmatrix.sync.aligned.m8n8.x4.shared.b16 {%0,%1,%2,%3}, [%4];"
                 : "=r"(r[0]), "=r"(r[1]), "=r"(r[2]), "=r"(r[3]) : "r"(addr));
}
__device__ __forceinline__ void ldsm2(uint32_t* r, uint32_t addr) {
    asm volatile("ldmatrix.sync.aligned.m8n8.x2.shared.b16 {%0,%1}, [%2];"
                 : "=r"(r[0]), "=r"(r[1]) : "r"(addr));
}
__device__ __forceinline__ void mma_bf16(float* c, const uint32_t* a, const uint32_t* b) {
    asm volatile(
        "mma.sync.aligned.m16n8k16.row.col.f32.bf16.bf16.f32 "
        "{%0,%1,%2,%3}, {%4,%5,%6,%7}, {%8,%9}, {%0,%1,%2,%3};"
        : "+f"(c[0]), "+f"(c[1]), "+f"(c[2]), "+f"(c[3])
        : "r"(a[0]), "r"(a[1]), "r"(a[2]), "r"(a[3]), "r"(b[0]), "r"(b[1]));
}
__device__ __forceinline__ void split1(float v, __nv_bfloat16& h, __nv_bfloat16& l) {
    h = __float2bfloat16_rn(v);
    l = __float2bfloat16_rn(v - __bfloat162float(h));
}

// ======================= HMMA GEMM (3-term bf16 split) =======================
// EXACT round-6 structure: 128x128 tile, BK=32, double-buffered cp.async,
// compile-time stage alternation, ldsm2 B loads. Only addition: optional Vb
// bf16 side-write for columns < 256 (voa GEMM's v section).
#define STAGE_BYTES 40960
#define ROW_ELT 40

__global__ __launch_bounds__(256)
void gemm_bf16x3(const __nv_bfloat16* __restrict__ Ah,
                 const __nv_bfloat16* __restrict__ Al,
                 const __nv_bfloat16* __restrict__ Bh,
                 const __nv_bfloat16* __restrict__ Bl,
                 const float* __restrict__ bias,
                 float* __restrict__ Cf,
                 __nv_bfloat16* __restrict__ Chi,
                 __nv_bfloat16* __restrict__ Clo,
                 __nv_bfloat16* __restrict__ Vb,
                 int K, int N, int do_relu)
{
    extern __shared__ __align__(128) char smem[];
    const uint32_t sb = smem_u32(smem);
    const int tid    = threadIdx.x;
    const int lane   = tid & 31;
    const int wid    = tid >> 5;
    const int warp_m = wid >> 2;
    const int warp_n = wid & 3;
    const int bm     = blockIdx.x * 128;
    const int bn     = blockIdx.y * 128;

    const __nv_bfloat16* gsrc[8];
    uint32_t soff[8];
    #pragma unroll
    for (int i = 0; i < 8; i++) {
        int q   = tid + i * 256;
        int arr = q >> 9;
        int rem = q & 511;
        int row = rem >> 2;
        int kc  = (rem & 3) << 3;
        const __nv_bfloat16* base =
            (arr == 0) ? Ah + (size_t)(bm + row) * K :
            (arr == 1) ? Al + (size_t)(bm + row) * K :
            (arr == 2) ? Bh + (size_t)(bn + row) * K :
                         Bl + (size_t)(bn + row) * K;
        gsrc[i] = base + kc;
        soff[i] = (uint32_t)(arr * 10240 + (row * ROW_ELT + kc) * 2);
    }

    float acc[4][4][4];
    #pragma unroll
    for (int mf = 0; mf < 4; mf++)
        #pragma unroll
        for (int nf = 0; nf < 4; nf++)
            #pragma unroll
            for (int j = 0; j < 4; j++) acc[mf][nf][j] = 0.f;

    const int nchunks = K >> 5;
    #pragma unroll
    for (int i = 0; i < 8; i++) cp16(sb + soff[i], gsrc[i]);
    cp_commit();

    const uint32_t a_r = (uint32_t)(lane & 15);
    const uint32_t a_c = (uint32_t)((lane >> 4) << 3);
    const uint32_t b_r = (uint32_t)(lane & 7);
    const uint32_t b_c = (uint32_t)(((lane >> 3) & 1) << 3);

    for (int c = 0; c < nchunks; c++) {
        const uint32_t st = sb + (uint32_t)(c & 1) * STAGE_BYTES;
        if (c + 1 < nchunks) {
            const uint32_t st2 = sb + (uint32_t)((c + 1) & 1) * STAGE_BYTES;
            int k0 = (c + 1) << 5;
            #pragma unroll
            for (int i = 0; i < 8; i++) cp16(st2 + soff[i], gsrc[i] + k0);
            cp_commit();
            cp_wait<1>();
        } else {
            cp_wait<0>();
        }
        __syncthreads();

        const uint32_t sAh = st;
        const uint32_t sAl = st + 10240;
        const uint32_t sBh = st + 20480;
        const uint32_t sBl = st + 30720;

        #pragma unroll
        for (int kk = 0; kk < 32; kk += 16) {
            uint32_t ah[4][4], al[4][4], bh[4][2], bl[4][2];
            #pragma unroll
            for (int mf = 0; mf < 4; mf++) {
                uint32_t r = (uint32_t)(warp_m * 64 + mf * 16) + a_r;
                uint32_t o = (r * ROW_ELT + (uint32_t)kk + a_c) * 2;
                ldsm4(ah[mf], sAh + o);
                ldsm4(al[mf], sAl + o);
            }
            #pragma unroll
            for (int nf = 0; nf < 4; nf++) {
                uint32_t r = (uint32_t)(warp_n * 32 + nf * 8) + b_r;
                uint32_t o = (r * ROW_ELT + (uint32_t)kk + b_c) * 2;
                ldsm2(bh[nf], sBh + o);
                ldsm2(bl[nf], sBl + o);
            }
            #pragma unroll
            for (int mf = 0; mf < 4; mf++)
                #pragma unroll
                for (int nf = 0; nf < 4; nf++) {
                    mma_bf16(acc[mf][nf], ah[mf], bh[nf]);
                    mma_bf16(acc[mf][nf], ah[mf], bl[nf]);
                    mma_bf16(acc[mf][nf], al[mf], bh[nf]);
                }
        }
        __syncthreads();
    }

    #pragma unroll
    for (int nf = 0; nf < 4; nf++) {
        int col = bn + warp_n * 32 + nf * 8 + ((lane & 3) << 1);
        float2 bi = *(const float2*)&bias[col];
        #pragma unroll
        for (int mf = 0; mf < 4; mf++) {
            int row0 = bm + warp_m * 64 + mf * 16 + (lane >> 2);
            float2 o0, o1;
            o0.x = acc[mf][nf][0] + bi.x;
            o0.y = acc[mf][nf][1] + bi.y;
            o1.x = acc[mf][nf][2] + bi.x;
            o1.y = acc[mf][nf][3] + bi.y;
            if (do_relu) {
                o0.x = fmaxf(o0.x, 0.f); o0.y = fmaxf(o0.y, 0.f);
                o1.x = fmaxf(o1.x, 0.f); o1.y = fmaxf(o1.y, 0.f);
            }
            if (Cf) {
                *(float2*)&Cf[(size_t)row0 * N + col]       = o0;
                *(float2*)&Cf[(size_t)(row0 + 8) * N + col] = o1;
            }
            if (Vb && col < 256) {
                *(__nv_bfloat162*)&Vb[(size_t)row0 * 256 + col] =
                    __floats2bfloat162_rn(o0.x, o0.y);
                *(__nv_bfloat162*)&Vb[(size_t)(row0 + 8) * 256 + col] =
                    __floats2bfloat162_rn(o1.x, o1.y);
            }
            if (Chi) {
                __nv_bfloat16 h0, l0, h1, l1;
                split1(o0.x, h0, l0); split1(o0.y, h1, l1);
                *(__nv_bfloat162*)&Chi[(size_t)row0 * N + col] = __halves2bfloat162(h0, h1);
                *(__nv_bfloat162*)&Clo[(size_t)row0 * N + col] = __halves2bfloat162(l0, l1);
                split1(o1.x, h0, l0); split1(o1.y, h1, l1);
                *(__nv_bfloat162*)&Chi[(size_t)(row0 + 8) * N + col] = __halves2bfloat162(h0, h1);
                *(__nv_bfloat162*)&Clo[(size_t)(row0 + 8) * N + col] = __halves2bfloat162(l0, l1);
            }
        }
    }
}

// ---------- one-shot weight convert + transpose + bias pack (all layers) ----
__global__ void conv_w_all(const float* __restrict__ Wv,  const float* __restrict__ Woff,
                           const float* __restrict__ Wat, const float* __restrict__ Wo,
                           const float* __restrict__ W1,  const float* __restrict__ W2,
                           const float* __restrict__ bv,  const float* __restrict__ boff,
                           const float* __restrict__ bat,
                           __nv_bfloat16* __restrict__ whi,
                           __nv_bfloat16* __restrict__ wlo,
                           float* __restrict__ bvoa)
{
    int idx = blockIdx.x * blockDim.x + threadIdx.x;
    if (idx < NLAY * 640) {
        int l = idx / 640, n = idx - l * 640;
        float b = (n < 256) ? bv[l * 256 + n]
                : (n < 512) ? boff[l * 256 + (n - 256)]
                            : bat[l * 128 + (n - 512)];
        bvoa[idx] = b;
    }
    if (idx >= NLAY * WTOT) return;
    int l = idx / WTOT, r = idx - l * WTOT;
    float v;
    if (r < VOA_SZ) {
        int n = r >> 8, k = r & 255;
        v = (n < 256) ? Wv  [(size_t)l * 65536 + k * 256 + n]
          : (n < 512) ? Woff[(size_t)l * 65536 + k * 256 + (n - 256)]
                      : Wat [(size_t)l * 32768 + k * 128 + (n - 512)];
    } else if (r < W1_OFF) {
        int j = r - WO_OFF; int n = j >> 8, k = j & 255;
        v = Wo[(size_t)l * 65536 + k * 256 + n];
    } else if (r < W2_OFF) {
        int j = r - W1_OFF; int n = j >> 8, k = j & 255;
        v = W1[(size_t)l * 262144 + k * 1024 + n];
    } else {
        int j = r - W2_OFF; int n = j >> 10, k = j & 1023;
        v = W2[(size_t)l * 262144 + k * 256 + n];
    }
    __nv_bfloat16 h, lo;
    split1(v, h, lo);
    whi[idx] = h;
    wlo[idx] = lo;
}

// ---------------- xp = x + pos, fused split (layer 0 only) ----------------
__global__ void add_pos_split(const float* __restrict__ x,
                              const float* __restrict__ pos,
                              float* __restrict__ xp,
                              __nv_bfloat16* __restrict__ hi,
                              __nv_bfloat16* __restrict__ lo, int n4)
{
    int i = blockIdx.x * blockDim.x + threadIdx.x;
    if (i >= n4) return;
    float4 a = ((const float4*)x)[i];
    float4 b = ((const float4*)pos)[i];
    a.x += b.x; a.y += b.y; a.z += b.z; a.w += b.w;
    ((float4*)xp)[i] = a;
    __nv_bfloat16 h0,l0,h1,l1,h2,l2,h3,l3;
    split1(a.x,h0,l0); split1(a.y,h1,l1); split1(a.z,h2,l2); split1(a.w,h3,l3);
    ((__nv_bfloat162*)hi)[2*i]   = __halves2bfloat162(h0,h1);
    ((__nv_bfloat162*)hi)[2*i+1] = __halves2bfloat162(h2,h3);
    ((__nv_bfloat162*)lo)[2*i]   = __halves2bfloat162(l0,l1);
    ((__nv_bfloat162*)lo)[2*i+1] = __halves2bfloat162(l2,l3);
}

// -------- deformable sampling: bf16 v gather, fused softmax, split out -----
__global__ void deform_sample_kernel(const float* __restrict__ refp,
                                     const float* __restrict__ voa,
                                     const __nv_bfloat16* __restrict__ vb,
                                     __nv_bfloat16* __restrict__ shi,
                                     __nv_bfloat16* __restrict__ slo)
{
    const int gw   = (blockIdx.x * blockDim.x + threadIdx.x) >> 5;
    const int lane = threadIdx.x & 31;
    if (gw >= NROW * NHEAD) return;
    const int row = gw >> 3;
    const int h   = gw & 7;
    const int b   = row / LQ;

    int   off00 = 0, dx = 0, dyv = 0;
    float cw00 = 0.f, cw01 = 0.f, cw10 = 0.f, cw11 = 0.f;
    {
        float lg = (lane < 16) ? voa[(size_t)row * 640 + 512 + h * 16 + lane]
                               : -1e30f;
        float m = lg;
        #pragma unroll
        for (int o = 8; o > 0; o >>= 1)
            m = fmaxf(m, __shfl_xor_sync(0xffffffffu, m, o, 16));
        float e = __expf(lg - m);
        float s = e;
        #pragma unroll
        for (int o = 8; o > 0; o >>= 1)
            s += __shfl_xor_sync(0xffffffffu, s, o, 16);
        float w = e / s;

        if (lane < 16) {
            int l  = lane >> 2;
            int Wl = 128 >> l;
            float wm1 = (float)(Wl - 1);
            float inv = 1.f / (float)Wl;
            const float* offp = voa + (size_t)row * 640 + 256 + h * 32 + lane * 2;
            float ox = offp[0], oy = offp[1];
            float refx = refp[row * 2], refy = refp[row * 2 + 1];
            float xs = (refx + ox * inv) * wm1;
            float ys = (refy + oy * inv) * wm1;
            xs = fminf(fmaxf(xs, 0.f), wm1);
            ys = fminf(fmaxf(ys, 0.f), wm1);
            float x0f = floorf(xs), y0f = floorf(ys);
            float wx = xs - x0f, wy = ys - y0f;
            int x0 = (int)x0f, y0 = (int)y0f;
            int x1 = min(x0 + 1, Wl - 1);
            int y1 = min(y0 + 1, Wl - 1);
            int lvlS = ((l >= 1) ? 16384 : 0) + ((l >= 2) ? 4096 : 0)
                     + ((l >= 3) ? 1024 : 0);
            off00 = (b * LQ + lvlS + y0 * Wl + x0) * 256;
            dx    = (x1 - x0) * 256;
            dyv   = (y1 - y0) * Wl * 256;
            float ax = 1.f - wx, ay = 1.f - wy;
            cw00 = w * ax * ay;
            cw01 = w * wx * ay;
            cw10 = w * ax * wy;
            cw11 = w * wx * wy;
        }
    }

    const __nv_bfloat16* vw = vb + h * 32 + lane;
    float acc = 0.f;
    #pragma unroll
    for (int s = 0; s < 16; s++) {
        int   o00 = __shfl_sync(0xffffffffu, off00, s);
        int   odx = __shfl_sync(0xffffffffu, dx,    s);
        int   ody = __shfl_sync(0xffffffffu, dyv,   s);
        float c00 = __shfl_sync(0xffffffffu, cw00,  s);
        float c01 = __shfl_sync(0xffffffffu, cw01,  s);
        float c10 = __shfl_sync(0xffffffffu, cw10,  s);
        float c11 = __shfl_sync(0xffffffffu, cw11,  s);
        float p00 = __bfloat162float(vw[o00]);
        float p01 = __bfloat162float(vw[o00 + odx]);
        float p10 = __bfloat162float(vw[o00 + ody]);
        float p11 = __bfloat162float(vw[o00 + ody + odx]);
        acc = fmaf(c00, p00, acc);
        acc = fmaf(c01, p01, acc);
        acc = fmaf(c10, p10, acc);
        acc = fmaf(c11, p11, acc);
    }
    __nv_bfloat16 hh, ll;
    split1(acc, hh, ll);
    shi[(size_t)row * 256 + h * 32 + lane] = hh;
    slo[(size_t)row * 256 + h * 32 + lane] = ll;
}

// -------- fused residual-add + LN, optional (+pos -> xp) and split --------
__global__ void add_ln_kernel(const float* __restrict__ a,
                              const float* __restrict__ b,
                              const float* __restrict__ gamma,
                              const float* __restrict__ beta,
                              float* __restrict__ out,
                              const float* __restrict__ pos,
                              float* __restrict__ xpf,
                              __nv_bfloat16* __restrict__ hi,
                              __nv_bfloat16* __restrict__ lo)
{
    const int warp = (blockIdx.x * blockDim.x + threadIdx.x) >> 5;
    const int lane = threadIdx.x & 31;
    if (warp >= NROW) return;
    const float* pa = a + (size_t)warp * CC;
    const float* pb = b + (size_t)warp * CC;

    float vals[8];
    float sum = 0.f, sq = 0.f;
    #pragma unroll
    for (int j = 0; j < 2; j++) {
        int idx = lane * 4 + j * 128;
        float4 va = *(const float4*)&pa[idx];
        float4 vb = *(const float4*)&pb[idx];
        float t0 = va.x + vb.x, t1 = va.y + vb.y;
        float t2 = va.z + vb.z, t3 = va.w + vb.w;
        vals[j*4+0]=t0; vals[j*4+1]=t1; vals[j*4+2]=t2; vals[j*4+3]=t3;
        sum += t0 + t1 + t2 + t3;
        sq  += t0*t0 + t1*t1 + t2*t2 + t3*t3;
    }
    #pragma unroll
    for (int o = 16; o > 0; o >>= 1) {
        sum += __shfl_xor_sync(0xffffffffu, sum, o);
        sq  += __shfl_xor_sync(0xffffffffu, sq,  o);
    }
    float mean = sum * (1.f / 256.f);
    float var  = sq * (1.f / 256.f) - mean * mean;
    float r    = rsqrtf(var + 1e-5f);

    #pragma unroll
    for (int j = 0; j < 2; j++) {
        int idx = lane * 4 + j * 128;
        size_t p = (size_t)warp * CC + idx;
        float4 g = *(const float4*)&gamma[idx];
        float4 bt = *(const float4*)&beta[idx];
        float4 o;
        o.x = (vals[j*4+0] - mean) * r * g.x + bt.x;
        o.y = (vals[j*4+1] - mean) * r * g.y + bt.y;
        o.z = (vals[j*4+2] - mean) * r * g.z + bt.z;
        o.w = (vals[j*4+3] - mean) * r * g.w + bt.w;
        *(float4*)&out[p] = o;
        float4 sv = o;
        if (xpf) {
            float4 pv = *(const float4*)&pos[p];
            sv.x += pv.x; sv.y += pv.y; sv.z += pv.z; sv.w += pv.w;
            *(float4*)&xpf[p] = sv;
        }
        if (hi) {
            __nv_bfloat16 h0,l0,h1,l1,h2,l2,h3,l3;
            split1(sv.x,h0,l0); split1(sv.y,h1,l1);
            split1(sv.z,h2,l2); split1(sv.w,h3,l3);
            *(__nv_bfloat162*)&hi[p]   = __halves2bfloat162(h0,h1);
            *(__nv_bfloat162*)&hi[p+2] = __halves2bfloat162(h2,h3);
            *(__nv_bfloat162*)&lo[p]   = __halves2bfloat162(l0,l1);
            *(__nv_bfloat162*)&lo[p+2] = __halves2bfloat162(l2,l3);
        }
    }
}

// ---------------- host orchestration ----------------
extern "C" void kernel_launch(void* const* d_in, const int* in_sizes, int n_in,
                              void* d_out, int out_size)
{
    const float* src  = (const float*)d_in[0];
    const float* pos  = (const float*)d_in[1];
    const float* refp = (const float*)d_in[2];
    const float* Woff = (const float*)d_in[3];
    const float* boff = (const float*)d_in[4];
    const float* Wat  = (const float*)d_in[5];
    const float* bat  = (const float*)d_in[6];
    const float* Wv   = (const float*)d_in[7];
    const float* bv   = (const float*)d_in[8];
    const float* Wo   = (const float*)d_in[9];
    const float* bo   = (const float*)d_in[10];
    const float* W1   = (const float*)d_in[11];
    const float* b1   = (const float*)d_in[12];
    const float* W2   = (const float*)d_in[13];
    const float* b2   = (const float*)d_in[14];
    const float* n1s  = (const float*)d_in[15];
    const float* n1b  = (const float*)d_in[16];
    const float* n2s  = (const float*)d_in[17];
    const float* n2b  = (const float*)d_in[18];
    float* x = (float*)d_out;

    float *xp, *voa, *tmp, *bvoa;
    __nv_bfloat16 *vb, *ahi, *alo, *bhi, *blo, *whi, *wlo;
    cudaGetSymbolAddress((void**)&xp,   g_xp);
    cudaGetSymbolAddress((void**)&voa,  g_voa);
    cudaGetSymbolAddress((void**)&tmp,  g_tmp);
    cudaGetSymbolAddress((void**)&vb,   g_vb);
    cudaGetSymbolAddress((void**)&ahi,  g_ahi);
    cudaGetSymbolAddress((void**)&alo,  g_alo);
    cudaGetSymbolAddress((void**)&bhi,  g_bhi);
    cudaGetSymbolAddress((void**)&blo,  g_blo);
    cudaGetSymbolAddress((void**)&whi,  g_whi);
    cudaGetSymbolAddress((void**)&wlo,  g_wlo);
    cudaGetSymbolAddress((void**)&bvoa, g_bvoa);

    const int GEMM_SMEM = 2 * STAGE_BYTES;   // 81920
    cudaFuncSetAttribute(gemm_bf16x3,
                         cudaFuncAttributeMaxDynamicSharedMemorySize, GEMM_SMEM);

    // one-shot weight conversion for ALL layers
    conv_w_all<<<(NLAY * WTOT + 255) / 256, 256>>>(
        Wv, Woff, Wat, Wo, W1, W2, bv, boff, bat, whi, wlo, bvoa);

    const int MB  = NROW / 128;       // 340
    const int n4c = NROW * CC / 4;

    // layer-0 xp = src + pos (+split); later layers get xp from fused LN2
    add_pos_split<<<(n4c + 255) / 256, 256>>>(src, pos, xp, ahi, alo, n4c);

    for (int i = 0; i < NLAY; i++) {
        const __nv_bfloat16* wh = whi + (size_t)i * WTOT;
        const __nv_bfloat16* wl = wlo + (size_t)i * WTOT;

        // fused v|off|att GEMM (N=640); also emits bf16 v copy for gather
        gemm_bf16x3<<<dim3(MB, 5), 256, GEMM_SMEM>>>(
            ahi, alo, wh, wl, bvoa + (size_t)i * 640,
            voa, nullptr, nullptr, vb, 256, 640, 0);

        // sampling (fused softmax) on bf16 v, emits samp split into ahi/alo
        deform_sample_kernel<<<(NROW * NHEAD * 32) / 256, 256>>>(refp, voa, vb, ahi, alo);

        // attn out proj -> tmp (f32)
        gemm_bf16x3<<<dim3(MB, 2), 256, GEMM_SMEM>>>(
            ahi, alo, wh + WO_OFF, wl + WO_OFF, bo + (size_t)i * CC,
            tmp, nullptr, nullptr, nullptr, 256, 256, 0);

        // x = LN(xp + attn), split(x) for FFN
        add_ln_kernel<<<(NROW * 32 + 255) / 256, 256>>>(
            xp, tmp, n1s + (size_t)i * CC, n1b + (size_t)i * CC, x,
            nullptr, nullptr, ahi, alo);

        // hidden = relu(x @ W1 + b1), split-only output
        gemm_bf16x3<<<dim3(MB, 8), 256, GEMM_SMEM>>>(
            ahi, alo, wh + W1_OFF, wl + W1_OFF, b1 + (size_t)i * FFD,
            nullptr, bhi, blo, nullptr, 256, 1024, 1);

        // f = hidden @ W2 + b2 -> tmp (f32)
        gemm_bf16x3<<<dim3(MB, 2), 256, GEMM_SMEM>>>(
            bhi, blo, wh + W2_OFF, wl + W2_OFF, b2 + (size_t)i * CC,
            tmp, nullptr, nullptr, nullptr, 1024, 256, 0);

        // x = LN(x + f); for layers 0..4 also emit xp = x + pos (+split)
        if (i < NLAY - 1) {
            add_ln_kernel<<<(NROW * 32 + 255) / 256, 256>>>(
                x, tmp, n2s + (size_t)i * CC, n2b + (size_t)i * CC, x,
                pos, xp, ahi, alo);
        } else {
            add_ln_kernel<<<(NROW * 32 + 255) / 256, 256>>>(
                x, tmp, n2s + (size_t)i * CC, n2b + (size_t)i * CC, x,
                nullptr, nullptr, nullptr, nullptr);
        }
    }
}